// round 7
// baseline (speedup 1.0000x reference)
#include <cuda_runtime.h>
#include <cuda_bf16.h>
#include <cstddef>

// Problem constants (fixed by setup_inputs)
#define BATCH 2
#define TSEQ  2048
#define EMB   1024
#define NH    16
#define HD    64
#define CHK   128
#define NC    (TSEQ / CHK)          // 16
#define MROWS (BATCH * TSEQ)        // 4096
#define EPS_F 1e-5f

// ---------------- scratch (static device allocations) ----------------
__device__ float g_Q[(size_t)MROWS * EMB];
__device__ float g_K[(size_t)MROWS * EMB];
__device__ float g_V[(size_t)MROWS * EMB];
__device__ float g_attn[(size_t)MROWS * EMB];
__device__ float g_S [(size_t)BATCH * NH * NC * HD * HD];   // per-chunk  k^T v
__device__ float g_Sp[(size_t)BATCH * NH * NC * HD * HD];   // exclusive prefix
__device__ float g_z [(size_t)BATCH * NH * NC * HD];
__device__ float g_zp[(size_t)BATCH * NH * NC * HD];

// ---------------- tiled SGEMM:  C[M,N] = act( A[M,K] @ B[N,K]^T ) ----------------
// ACT: 0 = none, 1 = elu+1 (phi), 2 = +bias
#define BM 128
#define BN 128
#define BKK 16
#define TM 8
#define TN 8

template <int ACT>
__global__ __launch_bounds__(256, 2)
void gemm_tn_kernel(const float* __restrict__ A, const float* __restrict__ Bw,
                    const float* __restrict__ bias, float* __restrict__ C,
                    int Mdim, int Ndim, int Kdim)
{
    __shared__ float As[BKK][BM];
    __shared__ float Bs[BKK][BN];

    const int tid = threadIdx.x;            // 256 threads
    const int tx = tid & 15;
    const int ty = tid >> 4;
    const int bm = blockIdx.y * BM;
    const int bn = blockIdx.x * BN;

    float acc[TM][TN];
#pragma unroll
    for (int i = 0; i < TM; i++)
#pragma unroll
        for (int j = 0; j < TN; j++) acc[i][j] = 0.f;

    const float* Ap = A  + (size_t)bm * Kdim;
    const float* Bp = Bw + (size_t)bn * Kdim;

    for (int k0 = 0; k0 < Kdim; k0 += BKK) {
#pragma unroll
        for (int it = 0; it < 2; it++) {
            int idx = tid + it * 256;       // 0..511 float4 slots (128 rows x 4)
            int r   = idx >> 2;
            int cq  = (idx & 3) * 4;
            float4 va = *(const float4*)(Ap + (size_t)r * Kdim + k0 + cq);
            As[cq + 0][r] = va.x; As[cq + 1][r] = va.y;
            As[cq + 2][r] = va.z; As[cq + 3][r] = va.w;
            float4 vb = *(const float4*)(Bp + (size_t)r * Kdim + k0 + cq);
            Bs[cq + 0][r] = vb.x; Bs[cq + 1][r] = vb.y;
            Bs[cq + 2][r] = vb.z; Bs[cq + 3][r] = vb.w;
        }
        __syncthreads();

#pragma unroll
        for (int kk = 0; kk < BKK; kk++) {
            float ra[TM], rb[TN];
#pragma unroll
            for (int i = 0; i < TM; i++) ra[i] = As[kk][ty * TM + i];
#pragma unroll
            for (int j = 0; j < TN; j++) rb[j] = Bs[kk][tx * TN + j];
#pragma unroll
            for (int i = 0; i < TM; i++)
#pragma unroll
                for (int j = 0; j < TN; j++)
                    acc[i][j] = fmaf(ra[i], rb[j], acc[i][j]);
        }
        __syncthreads();
    }

#pragma unroll
    for (int i = 0; i < TM; i++) {
        int row = bm + ty * TM + i;
#pragma unroll
        for (int j = 0; j < TN; j++) {
            int col = bn + tx * TN + j;
            float v = acc[i][j];
            if (ACT == 1) v = (v > 0.f) ? (v + 1.f) : expf(v);   // elu(x)+1
            if (ACT == 2) v += bias[col];
            C[(size_t)row * Ndim + col] = v;
        }
    }
}

// ---------------- Phase A: per-chunk stats  S_c = k^T v,  z_c = sum_j k ----------------
__global__ __launch_bounds__(256)
void chunk_stats_kernel(const float* __restrict__ K, const float* __restrict__ V,
                        float* __restrict__ gS, float* __restrict__ gZ)
{
    __shared__ float Ks[CHK][HD];
    __shared__ float Vs[CHK][HD];

    const int blk = blockIdx.x;             // bh*NC + c
    const int c   = blk % NC;
    const int bh  = blk / NC;
    const int b   = bh / NH;
    const int h   = bh % NH;
    const int tid = threadIdx.x;

    const size_t base = ((size_t)(b * TSEQ) + (size_t)c * CHK) * EMB + (size_t)h * HD;

#pragma unroll
    for (int it = 0; it < 8; it++) {
        int idx = tid + it * 256;           // 2048 float4 slots (128 rows x 16)
        int r = idx >> 4, q4 = (idx & 15) * 4;
        *(float4*)&Ks[r][q4] = *(const float4*)(K + base + (size_t)r * EMB + q4);
        *(float4*)&Vs[r][q4] = *(const float4*)(V + base + (size_t)r * EMB + q4);
    }
    __syncthreads();

    const int tx = tid & 15, ty = tid >> 4;   // each thread: 4x4 of 64x64
    float acc[4][4];
#pragma unroll
    for (int i = 0; i < 4; i++)
#pragma unroll
        for (int e = 0; e < 4; e++) acc[i][e] = 0.f;

    for (int j = 0; j < CHK; j++) {
        float rk[4], rv[4];
#pragma unroll
        for (int i = 0; i < 4; i++) rk[i] = Ks[j][ty * 4 + i];
#pragma unroll
        for (int e = 0; e < 4; e++) rv[e] = Vs[j][tx * 4 + e];
#pragma unroll
        for (int i = 0; i < 4; i++)
#pragma unroll
            for (int e = 0; e < 4; e++)
                acc[i][e] = fmaf(rk[i], rv[e], acc[i][e]);
    }

    float* Sout = gS + (size_t)blk * (HD * HD);
#pragma unroll
    for (int i = 0; i < 4; i++)
#pragma unroll
        for (int e = 0; e < 4; e++)
            Sout[(ty * 4 + i) * HD + tx * 4 + e] = acc[i][e];

    if (tid < HD) {
        float z = 0.f;
        for (int j = 0; j < CHK; j++) z += Ks[j][tid];
        gZ[(size_t)blk * HD + tid] = z;
    }
}

// ---------------- Phase B: exclusive prefix over chunks ----------------
__global__ __launch_bounds__(256)
void prefix_kernel(const float* __restrict__ gS, const float* __restrict__ gZ,
                   float* __restrict__ gSp, float* __restrict__ gZp)
{
    const int bh  = blockIdx.x;
    const int tid = threadIdx.x;

    float acc[16];
#pragma unroll
    for (int i = 0; i < 16; i++) acc[i] = 0.f;

    for (int c = 0; c < NC; c++) {
        size_t off = ((size_t)bh * NC + c) * (HD * HD);
#pragma unroll
        for (int i = 0; i < 16; i++) {
            gSp[off + tid * 16 + i] = acc[i];
            acc[i] += gS[off + tid * 16 + i];
        }
    }
    if (tid < HD) {
        float z = 0.f;
        for (int c = 0; c < NC; c++) {
            size_t off = ((size_t)bh * NC + c) * HD;
            gZp[off + tid] = z;
            z += gZ[off + tid];
        }
    }
}

// ---------------- Phase C: per-chunk output ----------------
// out[i,e] = ( A@v + q@Sp ) / ( rowsum(A) + q.zp + eps ),  A = (q k^T) * causal_mask
// Dynamic smem layout (floats):
//   Qt[64][128]  Kt[64][128](->reused Vs[128][64])  As[128][129]  Ss[64][64]
//   zc[64]  rsP[128][17]  den[128]
#define SM_QT   0
#define SM_KT   (SM_QT + 64 * 128)
#define SM_AS   (SM_KT + 64 * 128)
#define SM_SS   (SM_AS + 128 * 129)
#define SM_ZC   (SM_SS + 64 * 64)
#define SM_RSP  (SM_ZC + 64)
#define SM_DEN  (SM_RSP + 128 * 17)
#define SM_TOT  (SM_DEN + 128)
#define SMEM_BYTES_C (SM_TOT * 4)

__global__ __launch_bounds__(256)
void attn_out_kernel(const float* __restrict__ Q, const float* __restrict__ K,
                     const float* __restrict__ V,
                     const float* __restrict__ gSp, const float* __restrict__ gZp,
                     float* __restrict__ Aout)
{
    extern __shared__ float sm[];
    float* Qt  = sm + SM_QT;
    float* Kt  = sm + SM_KT;
    float* As  = sm + SM_AS;
    float* Ss  = sm + SM_SS;
    float* zc  = sm + SM_ZC;
    float* rsP = sm + SM_RSP;
    float* den = sm + SM_DEN;

    const int blk = blockIdx.x;             // bh*NC + c
    const int c   = blk % NC;
    const int bh  = blk / NC;
    const int b   = bh / NH;
    const int h   = bh % NH;
    const int tid = threadIdx.x;

    const size_t base = ((size_t)(b * TSEQ) + (size_t)c * CHK) * EMB + (size_t)h * HD;

    // Load Q,K transposed: Qt[dd][i], Kt[dd][j]
#pragma unroll
    for (int it = 0; it < 8; it++) {
        int idx = tid + it * 256;           // 2048 float4 slots
        int r = idx >> 4, q4 = (idx & 15) * 4;
        float4 vq = *(const float4*)(Q + base + (size_t)r * EMB + q4);
        Qt[(q4 + 0) * 128 + r] = vq.x; Qt[(q4 + 1) * 128 + r] = vq.y;
        Qt[(q4 + 2) * 128 + r] = vq.z; Qt[(q4 + 3) * 128 + r] = vq.w;
        float4 vk = *(const float4*)(K + base + (size_t)r * EMB + q4);
        Kt[(q4 + 0) * 128 + r] = vk.x; Kt[(q4 + 1) * 128 + r] = vk.y;
        Kt[(q4 + 2) * 128 + r] = vk.z; Kt[(q4 + 3) * 128 + r] = vk.w;
    }
    // Prefix state
    {
        size_t soff = (size_t)blk * (HD * HD);
#pragma unroll
        for (int it = 0; it < 4; it++) {
            int idx = tid + it * 256;       // 1024 float4 -> 4096 floats
            *(float4*)&Ss[idx * 4] = *(const float4*)(gSp + soff + idx * 4);
        }
        if (tid < HD) zc[tid] = gZp[(size_t)blk * HD + tid];
    }
    __syncthreads();

    const int tx = tid & 15, ty = tid >> 4;

    // A = Qt^T Kt with causal mask; partial row sums
    {
        float a[8][8];
#pragma unroll
        for (int i = 0; i < 8; i++)
#pragma unroll
            for (int j = 0; j < 8; j++) a[i][j] = 0.f;

        for (int dd = 0; dd < HD; dd++) {
            float rq[8], rk[8];
#pragma unroll
            for (int i = 0; i < 8; i++) rq[i] = Qt[dd * 128 + ty * 8 + i];
#pragma unroll
            for (int j = 0; j < 8; j++) rk[j] = Kt[dd * 128 + tx * 8 + j];
#pragma unroll
            for (int i = 0; i < 8; i++)
#pragma unroll
                for (int j = 0; j < 8; j++)
                    a[i][j] = fmaf(rq[i], rk[j], a[i][j]);
        }
#pragma unroll
        for (int i = 0; i < 8; i++) {
            int row = ty * 8 + i;
            float rsum = 0.f;
#pragma unroll
            for (int j = 0; j < 8; j++) {
                int col = tx * 8 + j;
                float v = (col <= row) ? a[i][j] : 0.f;
                As[row * 129 + col] = v;
                rsum += v;
            }
            rsP[row * 17 + tx] = rsum;
        }
    }
    __syncthreads();

    // Reuse Kt region as Vs[128][64]; compute den in parallel
    float* Vs = Kt;
#pragma unroll
    for (int it = 0; it < 8; it++) {
        int idx = tid + it * 256;
        int r = idx >> 4, q4 = (idx & 15) * 4;
        *(float4*)&Vs[r * 64 + q4] = *(const float4*)(V + base + (size_t)r * EMB + q4);
    }
    if (tid < CHK) {
        float rs = 0.f;
#pragma unroll
        for (int p = 0; p < 16; p++) rs += rsP[tid * 17 + p];
        float qz = 0.f;
        for (int dd = 0; dd < HD; dd++) qz += Qt[dd * 128 + tid] * zc[dd];
        den[tid] = rs + qz + EPS_F;
    }
    __syncthreads();

    // num = A@V + Qt^T@Ss ; thread owns 8 rows x 4 cols
    float num[8][4];
#pragma unroll
    for (int i = 0; i < 8; i++)
#pragma unroll
        for (int e = 0; e < 4; e++) num[i][e] = 0.f;

    for (int j = 0; j < CHK; j++) {
        float ra[8], rv[4];
#pragma unroll
        for (int i = 0; i < 8; i++) ra[i] = As[(ty * 8 + i) * 129 + j];
#pragma unroll
        for (int e = 0; e < 4; e++) rv[e] = Vs[j * 64 + tx * 4 + e];
#pragma unroll
        for (int i = 0; i < 8; i++)
#pragma unroll
            for (int e = 0; e < 4; e++)
                num[i][e] = fmaf(ra[i], rv[e], num[i][e]);
    }
    for (int dd = 0; dd < HD; dd++) {
        float rq[8], rs2[4];
#pragma unroll
        for (int i = 0; i < 8; i++) rq[i] = Qt[dd * 128 + ty * 8 + i];
#pragma unroll
        for (int e = 0; e < 4; e++) rs2[e] = Ss[dd * 64 + tx * 4 + e];
#pragma unroll
        for (int i = 0; i < 8; i++)
#pragma unroll
            for (int e = 0; e < 4; e++)
                num[i][e] = fmaf(rq[i], rs2[e], num[i][e]);
    }

#pragma unroll
    for (int i = 0; i < 8; i++) {
        int row = ty * 8 + i;
        float inv = 1.f / den[row];
#pragma unroll
        for (int e = 0; e < 4; e++) {
            int col = tx * 4 + e;
            Aout[base + (size_t)row * EMB + col] = num[i][e] * inv;
        }
    }
}

// ---------------- launch ----------------
extern "C" void kernel_launch(void* const* d_in, const int* in_sizes, int n_in,
                              void* d_out, int out_size)
{
    const float* x  = (const float*)d_in[0];
    const float* Wq = (const float*)d_in[1];
    const float* Wk = (const float*)d_in[2];
    const float* Wv = (const float*)d_in[3];
    const float* Wo = (const float*)d_in[4];
    const float* bo = (const float*)d_in[5];
    float* out = (float*)d_out;
    (void)in_sizes; (void)n_in; (void)out_size;

    float *pQ, *pK, *pV, *pA, *pS, *pSp, *pZ, *pZp;
    cudaGetSymbolAddress((void**)&pQ,  g_Q);
    cudaGetSymbolAddress((void**)&pK,  g_K);
    cudaGetSymbolAddress((void**)&pV,  g_V);
    cudaGetSymbolAddress((void**)&pA,  g_attn);
    cudaGetSymbolAddress((void**)&pS,  g_S);
    cudaGetSymbolAddress((void**)&pSp, g_Sp);
    cudaGetSymbolAddress((void**)&pZ,  g_z);
    cudaGetSymbolAddress((void**)&pZp, g_zp);

    cudaFuncSetAttribute(attn_out_kernel,
                         cudaFuncAttributeMaxDynamicSharedMemorySize, SMEM_BYTES_C);

    dim3 ggrid(EMB / BN, MROWS / BM);    // (8, 32)

    // Projections (phi fused for Q,K)
    gemm_tn_kernel<1><<<ggrid, 256>>>(x, Wq, nullptr, pQ, MROWS, EMB, EMB);
    gemm_tn_kernel<1><<<ggrid, 256>>>(x, Wk, nullptr, pK, MROWS, EMB, EMB);
    gemm_tn_kernel<0><<<ggrid, 256>>>(x, Wv, nullptr, pV, MROWS, EMB, EMB);

    // Chunked recurrent state: stats -> prefix -> output
    chunk_stats_kernel<<<BATCH * NH * NC, 256>>>(pK, pV, pS, pZ);
    prefix_kernel<<<BATCH * NH, 256>>>(pS, pZ, pSp, pZp);
    attn_out_kernel<<<BATCH * NH * NC, 256, SMEM_BYTES_C>>>(pQ, pK, pV, pSp, pZp, pA);

    // Output projection + bias
    gemm_tn_kernel<2><<<ggrid, 256>>>(pA, Wo, bo, out, MROWS, EMB, EMB);
}

// round 9
// speedup vs baseline: 2.2322x; 2.2322x over previous
#include <cuda_runtime.h>
#include <cuda_bf16.h>
#include <cstdint>
#include <cstddef>

// Problem constants (fixed by setup_inputs)
#define BATCH 2
#define TSEQ  2048
#define EMB   1024
#define NH    16
#define HD    64
#define CHK   128
#define NC    (TSEQ / CHK)          // 16
#define MROWS (BATCH * TSEQ)        // 4096
#define EPS_F 1e-5f

// ---------------- scratch (static device allocations) ----------------
__device__ float g_Q[(size_t)MROWS * EMB];
__device__ float g_K[(size_t)MROWS * EMB];
__device__ float g_V[(size_t)MROWS * EMB];
__device__ float g_attn[(size_t)MROWS * EMB];
__device__ float g_S [(size_t)BATCH * NH * NC * HD * HD];   // per-chunk  k^T v
__device__ float g_Sp[(size_t)BATCH * NH * NC * HD * HD];   // exclusive prefix
__device__ float g_z [(size_t)BATCH * NH * NC * HD];
__device__ float g_zp[(size_t)BATCH * NH * NC * HD];

// bf16 hi/lo split operands for tensor-core GEMMs
__device__ __nv_bfloat16 g_xh[(size_t)MROWS * EMB];
__device__ __nv_bfloat16 g_xl[(size_t)MROWS * EMB];
__device__ __nv_bfloat16 g_ah[(size_t)MROWS * EMB];
__device__ __nv_bfloat16 g_al[(size_t)MROWS * EMB];
__device__ __nv_bfloat16 g_wqh[(size_t)EMB * EMB];
__device__ __nv_bfloat16 g_wql[(size_t)EMB * EMB];
__device__ __nv_bfloat16 g_wkh[(size_t)EMB * EMB];
__device__ __nv_bfloat16 g_wkl[(size_t)EMB * EMB];
__device__ __nv_bfloat16 g_wvh[(size_t)EMB * EMB];
__device__ __nv_bfloat16 g_wvl[(size_t)EMB * EMB];
__device__ __nv_bfloat16 g_woh[(size_t)EMB * EMB];
__device__ __nv_bfloat16 g_wol[(size_t)EMB * EMB];

// ---------------- PTX helpers (arch-agnostic: valid on target sm_103) ----------------
__device__ __forceinline__ uint32_t smem_u32(const void* p) {
    uint32_t a;
    asm("{ .reg .u64 t; cvta.to.shared.u64 t, %1; cvt.u32.u64 %0, t; }"
        : "=r"(a) : "l"(p));
    return a;
}
__device__ __forceinline__ void cp16(uint32_t s, const void* g) {
    asm volatile("cp.async.cg.shared.global [%0], [%1], 16;" :: "r"(s), "l"(g) : "memory");
}
__device__ __forceinline__ void cp_commit() {
    asm volatile("cp.async.commit_group;" ::: "memory");
}
__device__ __forceinline__ void cp_wait0() {
    asm volatile("cp.async.wait_group 0;" ::: "memory");
}
__device__ __forceinline__ void cp_wait1() {
    asm volatile("cp.async.wait_group 1;" ::: "memory");
}
__device__ __forceinline__ void ldmx4(uint32_t* r, uint32_t addr) {
    asm volatile("ldmatrix.sync.aligned.m8n8.x4.shared.b16 {%0,%1,%2,%3}, [%4];"
                 : "=r"(r[0]), "=r"(r[1]), "=r"(r[2]), "=r"(r[3]) : "r"(addr));
}
__device__ __forceinline__ void mma_bf16(float* c, const uint32_t* a, const uint32_t* b) {
    asm volatile("mma.sync.aligned.m16n8k16.row.col.f32.bf16.bf16.f32 "
                 "{%0,%1,%2,%3},{%4,%5,%6,%7},{%8,%9},{%0,%1,%2,%3};"
                 : "+f"(c[0]), "+f"(c[1]), "+f"(c[2]), "+f"(c[3])
                 : "r"(a[0]), "r"(a[1]), "r"(a[2]), "r"(a[3]), "r"(b[0]), "r"(b[1]));
}

// ---------------- hi/lo bf16 split ----------------
__global__ __launch_bounds__(256)
void split_bf16_kernel(const float* __restrict__ in,
                       __nv_bfloat16* __restrict__ hi, __nv_bfloat16* __restrict__ lo,
                       int n4)
{
    int i = blockIdx.x * 256 + threadIdx.x;
    if (i >= n4) return;
    float4 v = reinterpret_cast<const float4*>(in)[i];
    __nv_bfloat16 h0 = __float2bfloat16(v.x);
    __nv_bfloat16 h1 = __float2bfloat16(v.y);
    __nv_bfloat16 h2 = __float2bfloat16(v.z);
    __nv_bfloat16 h3 = __float2bfloat16(v.w);
    __nv_bfloat16 l0 = __float2bfloat16(v.x - __bfloat162float(h0));
    __nv_bfloat16 l1 = __float2bfloat16(v.y - __bfloat162float(h1));
    __nv_bfloat16 l2 = __float2bfloat16(v.z - __bfloat162float(h2));
    __nv_bfloat16 l3 = __float2bfloat16(v.w - __bfloat162float(h3));
    reinterpret_cast<__nv_bfloat162*>(hi)[2 * i + 0] = __halves2bfloat162(h0, h1);
    reinterpret_cast<__nv_bfloat162*>(hi)[2 * i + 1] = __halves2bfloat162(h2, h3);
    reinterpret_cast<__nv_bfloat162*>(lo)[2 * i + 0] = __halves2bfloat162(l0, l1);
    reinterpret_cast<__nv_bfloat162*>(lo)[2 * i + 1] = __halves2bfloat162(l2, l3);
}

// ---------------- mma.sync bf16 hi/lo GEMM: C[M,N] = act( A @ W^T ) ----------------
// Tile 128x128, BK=64 bf16, 8 warps (4m x 2n), warp tile 32x64.
// Smem rows padded to 72 bf16 (144 B) -> ldmatrix conflict-free.
// ACT: 0 = none, 1 = elu+1, 2 = +bias
#define KC        64
#define NKC       (EMB / KC)            // 16
#define ROW_HALF  72                    // bf16 per smem row (64 + 8 pad)
#define ROW_B     (ROW_HALF * 2)        // 144 bytes
#define TILE_BY   (128 * ROW_B)         // 18432
#define STAGE_BY  (4 * TILE_BY)         // 73728 (Ah, Al, Bh, Bl)
#define GEMM_SMEM (2 * STAGE_BY)        // 147456

template <int ACT>
__global__ __launch_bounds__(256, 1)
void mma_gemm_kernel(const __nv_bfloat16* __restrict__ Ah, const __nv_bfloat16* __restrict__ Al,
                     const __nv_bfloat16* __restrict__ Bh, const __nv_bfloat16* __restrict__ Bl,
                     const float* __restrict__ bias, float* __restrict__ C)
{
    extern __shared__ char smem[];
    const uint32_t sb = smem_u32(smem);

    const int tid = threadIdx.x;
    const int wid = tid >> 5;
    const int lid = tid & 31;
    const int bm  = blockIdx.y * 128;
    const int bn  = blockIdx.x * 128;

    const int wm = wid & 3;             // 0..3 -> m offset
    const int wn = wid >> 2;            // 0..1 -> n offset
    const int m_off = wm * 32;
    const int n_off = wn * 64;

    // ldmatrix per-lane address components
    const int q   = lid >> 3;
    const int a_r = ((q & 1) << 3) + (lid & 7);
    const int a_c = (q >> 1) << 3;
    const int b_r = ((q >> 1) << 3) + (lid & 7);
    const int b_c = (q & 1) << 3;

    // cp.async per-lane mapping (16 vectors of 16B per thread per chunk)
    // idx -> tile t (0..3), row r (0..127), kvec c (0..7)
    auto load_chunk = [&](int kc, int stg) {
#pragma unroll
        for (int it = 0; it < 16; it++) {
            int idx = tid + it * 256;
            int t = idx >> 10;
            int r = (idx >> 3) & 127;
            int c = idx & 7;
            uint32_t saddr = sb + stg * STAGE_BY + t * TILE_BY + r * ROW_B + c * 16;
            const __nv_bfloat16* src = (t == 0) ? Ah : (t == 1) ? Al : (t == 2) ? Bh : Bl;
            int grow = (t < 2) ? (bm + r) : (bn + r);
            cp16(saddr, src + (size_t)grow * EMB + kc * KC + c * 8);
        }
        cp_commit();
    };

    float acc[2][8][4];
#pragma unroll
    for (int mt = 0; mt < 2; mt++)
#pragma unroll
        for (int nt = 0; nt < 8; nt++)
#pragma unroll
            for (int e = 0; e < 4; e++) acc[mt][nt][e] = 0.f;

    load_chunk(0, 0);

    for (int kc = 0; kc < NKC; kc++) {
        if (kc + 1 < NKC) { load_chunk(kc + 1, (kc + 1) & 1); cp_wait1(); }
        else              { cp_wait0(); }
        __syncthreads();

        const uint32_t uAh = sb + (kc & 1) * STAGE_BY;
        const uint32_t uAl = uAh + TILE_BY;
        const uint32_t uBh = uAl + TILE_BY;
        const uint32_t uBl = uBh + TILE_BY;

#pragma unroll
        for (int ks = 0; ks < 4; ks++) {
            const int kcol2 = (ks * 16) * 2;

            uint32_t af[2][4];
#pragma unroll
            for (int mt = 0; mt < 2; mt++)
                ldmx4(af[mt], uAh + (m_off + mt * 16 + a_r) * ROW_B + kcol2 + a_c * 2);

            uint32_t bh_[4][4];
#pragma unroll
            for (int p = 0; p < 4; p++)
                ldmx4(bh_[p], uBh + (n_off + p * 16 + b_r) * ROW_B + kcol2 + b_c * 2);

            // hh
#pragma unroll
            for (int mt = 0; mt < 2; mt++)
#pragma unroll
                for (int nt = 0; nt < 8; nt++)
                    mma_bf16(acc[mt][nt], af[mt], &bh_[nt >> 1][(nt & 1) * 2]);

            // a_hi x b_lo
            uint32_t bl_[4][4];
#pragma unroll
            for (int p = 0; p < 4; p++)
                ldmx4(bl_[p], uBl + (n_off + p * 16 + b_r) * ROW_B + kcol2 + b_c * 2);
#pragma unroll
            for (int mt = 0; mt < 2; mt++)
#pragma unroll
                for (int nt = 0; nt < 8; nt++)
                    mma_bf16(acc[mt][nt], af[mt], &bl_[nt >> 1][(nt & 1) * 2]);

            // a_lo x b_hi (reuse af regs)
#pragma unroll
            for (int mt = 0; mt < 2; mt++)
                ldmx4(af[mt], uAl + (m_off + mt * 16 + a_r) * ROW_B + kcol2 + a_c * 2);
#pragma unroll
            for (int mt = 0; mt < 2; mt++)
#pragma unroll
                for (int nt = 0; nt < 8; nt++)
                    mma_bf16(acc[mt][nt], af[mt], &bh_[nt >> 1][(nt & 1) * 2]);
        }
        __syncthreads();
    }

    // Epilogue: direct global stores (float2 pairs, 8 sectors/instr fully used)
    const int gr  = lid >> 2;
    const int gc2 = (lid & 3) * 2;
#pragma unroll
    for (int mt = 0; mt < 2; mt++) {
#pragma unroll
        for (int nt = 0; nt < 8; nt++) {
            int row0 = bm + m_off + mt * 16 + gr;
            int col  = bn + n_off + nt * 8 + gc2;
            float2 v0 = make_float2(acc[mt][nt][0], acc[mt][nt][1]);
            float2 v1 = make_float2(acc[mt][nt][2], acc[mt][nt][3]);
            if (ACT == 1) {
                v0.x = (v0.x > 0.f) ? (v0.x + 1.f) : expf(v0.x);
                v0.y = (v0.y > 0.f) ? (v0.y + 1.f) : expf(v0.y);
                v1.x = (v1.x > 0.f) ? (v1.x + 1.f) : expf(v1.x);
                v1.y = (v1.y > 0.f) ? (v1.y + 1.f) : expf(v1.y);
            }
            if (ACT == 2) {
                float2 bv = *reinterpret_cast<const float2*>(bias + col);
                v0.x += bv.x; v0.y += bv.y;
                v1.x += bv.x; v1.y += bv.y;
            }
            *reinterpret_cast<float2*>(C + (size_t)row0 * EMB + col)       = v0;
            *reinterpret_cast<float2*>(C + (size_t)(row0 + 8) * EMB + col) = v1;
        }
    }
}

// ---------------- Phase A: per-chunk stats  S_c = k^T v,  z_c = sum_j k ----------------
__global__ __launch_bounds__(256)
void chunk_stats_kernel(const float* __restrict__ K, const float* __restrict__ V,
                        float* __restrict__ gS, float* __restrict__ gZ)
{
    __shared__ float Ks[CHK][HD];
    __shared__ float Vs[CHK][HD];

    const int blk = blockIdx.x;
    const int c   = blk % NC;
    const int bh  = blk / NC;
    const int b   = bh / NH;
    const int h   = bh % NH;
    const int tid = threadIdx.x;

    const size_t base = ((size_t)(b * TSEQ) + (size_t)c * CHK) * EMB + (size_t)h * HD;

#pragma unroll
    for (int it = 0; it < 8; it++) {
        int idx = tid + it * 256;
        int r = idx >> 4, q4 = (idx & 15) * 4;
        *(float4*)&Ks[r][q4] = *(const float4*)(K + base + (size_t)r * EMB + q4);
        *(float4*)&Vs[r][q4] = *(const float4*)(V + base + (size_t)r * EMB + q4);
    }
    __syncthreads();

    const int tx = tid & 15, ty = tid >> 4;
    float acc[4][4];
#pragma unroll
    for (int i = 0; i < 4; i++)
#pragma unroll
        for (int e = 0; e < 4; e++) acc[i][e] = 0.f;

    for (int j = 0; j < CHK; j++) {
        float rk[4], rv[4];
#pragma unroll
        for (int i = 0; i < 4; i++) rk[i] = Ks[j][ty * 4 + i];
#pragma unroll
        for (int e = 0; e < 4; e++) rv[e] = Vs[j][tx * 4 + e];
#pragma unroll
        for (int i = 0; i < 4; i++)
#pragma unroll
            for (int e = 0; e < 4; e++)
                acc[i][e] = fmaf(rk[i], rv[e], acc[i][e]);
    }

    float* Sout = gS + (size_t)blk * (HD * HD);
#pragma unroll
    for (int i = 0; i < 4; i++)
#pragma unroll
        for (int e = 0; e < 4; e++)
            Sout[(ty * 4 + i) * HD + tx * 4 + e] = acc[i][e];

    if (tid < HD) {
        float z = 0.f;
        for (int j = 0; j < CHK; j++) z += Ks[j][tid];
        gZ[(size_t)blk * HD + tid] = z;
    }
}

// ---------------- Phase B: exclusive prefix over chunks ----------------
__global__ __launch_bounds__(256)
void prefix_kernel(const float* __restrict__ gS, const float* __restrict__ gZ,
                   float* __restrict__ gSp, float* __restrict__ gZp)
{
    const int bh  = blockIdx.x;
    const int tid = threadIdx.x;

    float acc[16];
#pragma unroll
    for (int i = 0; i < 16; i++) acc[i] = 0.f;

    for (int c = 0; c < NC; c++) {
        size_t off = ((size_t)bh * NC + c) * (HD * HD);
#pragma unroll
        for (int i = 0; i < 16; i++) {
            gSp[off + tid * 16 + i] = acc[i];
            acc[i] += gS[off + tid * 16 + i];
        }
    }
    if (tid < HD) {
        float z = 0.f;
        for (int c = 0; c < NC; c++) {
            size_t off = ((size_t)bh * NC + c) * HD;
            gZp[off + tid] = z;
            z += gZ[off + tid];
        }
    }
}

// ---------------- Phase C: per-chunk output ----------------
#define SM_QT   0
#define SM_KT   (SM_QT + 64 * 128)
#define SM_AS   (SM_KT + 64 * 128)
#define SM_SS   (SM_AS + 128 * 129)
#define SM_ZC   (SM_SS + 64 * 64)
#define SM_RSP  (SM_ZC + 64)
#define SM_DEN  (SM_RSP + 128 * 17)
#define SM_TOT  (SM_DEN + 128)
#define SMEM_BYTES_C (SM_TOT * 4)

__global__ __launch_bounds__(256)
void attn_out_kernel(const float* __restrict__ Q, const float* __restrict__ K,
                     const float* __restrict__ V,
                     const float* __restrict__ gSp, const float* __restrict__ gZp,
                     float* __restrict__ Aout)
{
    extern __shared__ float sm[];
    float* Qt  = sm + SM_QT;
    float* Kt  = sm + SM_KT;
    float* As  = sm + SM_AS;
    float* Ss  = sm + SM_SS;
    float* zc  = sm + SM_ZC;
    float* rsP = sm + SM_RSP;
    float* den = sm + SM_DEN;

    const int blk = blockIdx.x;
    const int c   = blk % NC;
    const int bh  = blk / NC;
    const int b   = bh / NH;
    const int h   = bh % NH;
    const int tid = threadIdx.x;

    const size_t base = ((size_t)(b * TSEQ) + (size_t)c * CHK) * EMB + (size_t)h * HD;

#pragma unroll
    for (int it = 0; it < 8; it++) {
        int idx = tid + it * 256;
        int r = idx >> 4, q4 = (idx & 15) * 4;
        float4 vq = *(const float4*)(Q + base + (size_t)r * EMB + q4);
        Qt[(q4 + 0) * 128 + r] = vq.x; Qt[(q4 + 1) * 128 + r] = vq.y;
        Qt[(q4 + 2) * 128 + r] = vq.z; Qt[(q4 + 3) * 128 + r] = vq.w;
        float4 vk = *(const float4*)(K + base + (size_t)r * EMB + q4);
        Kt[(q4 + 0) * 128 + r] = vk.x; Kt[(q4 + 1) * 128 + r] = vk.y;
        Kt[(q4 + 2) * 128 + r] = vk.z; Kt[(q4 + 3) * 128 + r] = vk.w;
    }
    {
        size_t soff = (size_t)blk * (HD * HD);
#pragma unroll
        for (int it = 0; it < 4; it++) {
            int idx = tid + it * 256;
            *(float4*)&Ss[idx * 4] = *(const float4*)(gSp + soff + idx * 4);
        }
        if (tid < HD) zc[tid] = gZp[(size_t)blk * HD + tid];
    }
    __syncthreads();

    const int tx = tid & 15, ty = tid >> 4;

    {
        float a[8][8];
#pragma unroll
        for (int i = 0; i < 8; i++)
#pragma unroll
            for (int j = 0; j < 8; j++) a[i][j] = 0.f;

        for (int dd = 0; dd < HD; dd++) {
            float rq[8], rk[8];
#pragma unroll
            for (int i = 0; i < 8; i++) rq[i] = Qt[dd * 128 + ty * 8 + i];
#pragma unroll
            for (int j = 0; j < 8; j++) rk[j] = Kt[dd * 128 + tx * 8 + j];
#pragma unroll
            for (int i = 0; i < 8; i++)
#pragma unroll
                for (int j = 0; j < 8; j++)
                    a[i][j] = fmaf(rq[i], rk[j], a[i][j]);
        }
#pragma unroll
        for (int i = 0; i < 8; i++) {
            int row = ty * 8 + i;
            float rsum = 0.f;
#pragma unroll
            for (int j = 0; j < 8; j++) {
                int col = tx * 8 + j;
                float v = (col <= row) ? a[i][j] : 0.f;
                As[row * 129 + col] = v;
                rsum += v;
            }
            rsP[row * 17 + tx] = rsum;
        }
    }
    __syncthreads();

    float* Vs = Kt;
#pragma unroll
    for (int it = 0; it < 8; it++) {
        int idx = tid + it * 256;
        int r = idx >> 4, q4 = (idx & 15) * 4;
        *(float4*)&Vs[r * 64 + q4] = *(const float4*)(V + base + (size_t)r * EMB + q4);
    }
    if (tid < CHK) {
        float rs = 0.f;
#pragma unroll
        for (int p = 0; p < 16; p++) rs += rsP[tid * 17 + p];
        float qz = 0.f;
        for (int dd = 0; dd < HD; dd++) qz += Qt[dd * 128 + tid] * zc[dd];
        den[tid] = rs + qz + EPS_F;
    }
    __syncthreads();

    float num[8][4];
#pragma unroll
    for (int i = 0; i < 8; i++)
#pragma unroll
        for (int e = 0; e < 4; e++) num[i][e] = 0.f;

    for (int j = 0; j < CHK; j++) {
        float ra[8], rv[4];
#pragma unroll
        for (int i = 0; i < 8; i++) ra[i] = As[(ty * 8 + i) * 129 + j];
#pragma unroll
        for (int e = 0; e < 4; e++) rv[e] = Vs[j * 64 + tx * 4 + e];
#pragma unroll
        for (int i = 0; i < 8; i++)
#pragma unroll
            for (int e = 0; e < 4; e++)
                num[i][e] = fmaf(ra[i], rv[e], num[i][e]);
    }
    for (int dd = 0; dd < HD; dd++) {
        float rq[8], rs2[4];
#pragma unroll
        for (int i = 0; i < 8; i++) rq[i] = Qt[dd * 128 + ty * 8 + i];
#pragma unroll
        for (int e = 0; e < 4; e++) rs2[e] = Ss[dd * 64 + tx * 4 + e];
#pragma unroll
        for (int i = 0; i < 8; i++)
#pragma unroll
            for (int e = 0; e < 4; e++)
                num[i][e] = fmaf(rq[i], rs2[e], num[i][e]);
    }

#pragma unroll
    for (int i = 0; i < 8; i++) {
        int row = ty * 8 + i;
        float inv = 1.f / den[row];
#pragma unroll
        for (int e = 0; e < 4; e++) {
            int col = tx * 4 + e;
            Aout[base + (size_t)row * EMB + col] = num[i][e] * inv;
        }
    }
}

// ---------------- launch ----------------
extern "C" void kernel_launch(void* const* d_in, const int* in_sizes, int n_in,
                              void* d_out, int out_size)
{
    const float* x  = (const float*)d_in[0];
    const float* Wq = (const float*)d_in[1];
    const float* Wk = (const float*)d_in[2];
    const float* Wv = (const float*)d_in[3];
    const float* Wo = (const float*)d_in[4];
    const float* bo = (const float*)d_in[5];
    float* out = (float*)d_out;
    (void)in_sizes; (void)n_in; (void)out_size;

    float *pQ, *pK, *pV, *pA, *pS, *pSp, *pZ, *pZp;
    cudaGetSymbolAddress((void**)&pQ,  g_Q);
    cudaGetSymbolAddress((void**)&pK,  g_K);
    cudaGetSymbolAddress((void**)&pV,  g_V);
    cudaGetSymbolAddress((void**)&pA,  g_attn);
    cudaGetSymbolAddress((void**)&pS,  g_S);
    cudaGetSymbolAddress((void**)&pSp, g_Sp);
    cudaGetSymbolAddress((void**)&pZ,  g_z);
    cudaGetSymbolAddress((void**)&pZp, g_zp);

    __nv_bfloat16 *xh, *xl, *ah, *al, *wqh, *wql, *wkh, *wkl, *wvh, *wvl, *woh, *wol;
    cudaGetSymbolAddress((void**)&xh,  g_xh);
    cudaGetSymbolAddress((void**)&xl,  g_xl);
    cudaGetSymbolAddress((void**)&ah,  g_ah);
    cudaGetSymbolAddress((void**)&al,  g_al);
    cudaGetSymbolAddress((void**)&wqh, g_wqh);
    cudaGetSymbolAddress((void**)&wql, g_wql);
    cudaGetSymbolAddress((void**)&wkh, g_wkh);
    cudaGetSymbolAddress((void**)&wkl, g_wkl);
    cudaGetSymbolAddress((void**)&wvh, g_wvh);
    cudaGetSymbolAddress((void**)&wvl, g_wvl);
    cudaGetSymbolAddress((void**)&woh, g_woh);
    cudaGetSymbolAddress((void**)&wol, g_wol);

    cudaFuncSetAttribute(attn_out_kernel,
                         cudaFuncAttributeMaxDynamicSharedMemorySize, SMEM_BYTES_C);
    cudaFuncSetAttribute(mma_gemm_kernel<0>,
                         cudaFuncAttributeMaxDynamicSharedMemorySize, GEMM_SMEM);
    cudaFuncSetAttribute(mma_gemm_kernel<1>,
                         cudaFuncAttributeMaxDynamicSharedMemorySize, GEMM_SMEM);
    cudaFuncSetAttribute(mma_gemm_kernel<2>,
                         cudaFuncAttributeMaxDynamicSharedMemorySize, GEMM_SMEM);

    const int n4x = MROWS * EMB / 4;   // 1048576
    const int n4w = EMB * EMB / 4;     // 262144

    // hi/lo splits
    split_bf16_kernel<<<n4x / 256, 256>>>(x,  xh,  xl,  n4x);
    split_bf16_kernel<<<n4w / 256, 256>>>(Wq, wqh, wql, n4w);
    split_bf16_kernel<<<n4w / 256, 256>>>(Wk, wkh, wkl, n4w);
    split_bf16_kernel<<<n4w / 256, 256>>>(Wv, wvh, wvl, n4w);
    split_bf16_kernel<<<n4w / 256, 256>>>(Wo, woh, wol, n4w);

    dim3 tgrid(EMB / 128, MROWS / 128);   // (8, 32)

    // Projections on mma.sync tensor cores (phi fused for Q,K)
    mma_gemm_kernel<1><<<tgrid, 256, GEMM_SMEM>>>(xh, xl, wqh, wql, nullptr, pQ);
    mma_gemm_kernel<1><<<tgrid, 256, GEMM_SMEM>>>(xh, xl, wkh, wkl, nullptr, pK);
    mma_gemm_kernel<0><<<tgrid, 256, GEMM_SMEM>>>(xh, xl, wvh, wvl, nullptr, pV);

    // Chunked recurrent state: stats -> prefix -> output
    chunk_stats_kernel<<<BATCH * NH * NC, 256>>>(pK, pV, pS, pZ);
    prefix_kernel<<<BATCH * NH, 256>>>(pS, pZ, pSp, pZp);
    attn_out_kernel<<<BATCH * NH * NC, 256, SMEM_BYTES_C>>>(pQ, pK, pV, pSp, pZp, pA);

    // Output projection + bias
    split_bf16_kernel<<<n4x / 256, 256>>>(pA, ah, al, n4x);
    mma_gemm_kernel<2><<<tgrid, 256, GEMM_SMEM>>>(ah, al, woh, wol, bo, out);
}

// round 10
// speedup vs baseline: 2.9826x; 1.3362x over previous
#include <cuda_runtime.h>
#include <cuda_fp16.h>
#include <cstdint>
#include <cstddef>

// Problem constants (fixed by setup_inputs)
#define BATCH 2
#define TSEQ  2048
#define EMB   1024
#define NH    16
#define HD    64
#define CHK   128
#define NC    (TSEQ / CHK)          // 16
#define MROWS (BATCH * TSEQ)        // 4096
#define EPS_F 1e-5f

// ---------------- scratch (static device allocations) ----------------
__device__ float g_Q[(size_t)MROWS * EMB];
__device__ float g_K[(size_t)MROWS * EMB];
__device__ float g_V[(size_t)MROWS * EMB];
__device__ float g_attn[(size_t)MROWS * EMB];
__device__ float g_S [(size_t)BATCH * NH * NC * HD * HD];   // per-chunk  k^T v
__device__ float g_Sp[(size_t)BATCH * NH * NC * HD * HD];   // exclusive prefix
__device__ float g_z [(size_t)BATCH * NH * NC * HD];
__device__ float g_zp[(size_t)BATCH * NH * NC * HD];

// fp16 operands for tensor-core GEMMs: A as hi/lo split, weights single fp16
__device__ __half g_xh[(size_t)MROWS * EMB];
__device__ __half g_xl[(size_t)MROWS * EMB];
__device__ __half g_ah[(size_t)MROWS * EMB];
__device__ __half g_al[(size_t)MROWS * EMB];
__device__ __half g_w [(size_t)4 * EMB * EMB];   // Wq, Wk, Wv, Wo (fp16)

// ---------------- PTX helpers (arch-agnostic: valid on target sm_103) ----------------
__device__ __forceinline__ uint32_t smem_u32(const void* p) {
    uint32_t a;
    asm("{ .reg .u64 t; cvta.to.shared.u64 t, %1; cvt.u32.u64 %0, t; }"
        : "=r"(a) : "l"(p));
    return a;
}
__device__ __forceinline__ void cp16(uint32_t s, const void* g) {
    asm volatile("cp.async.cg.shared.global [%0], [%1], 16;" :: "r"(s), "l"(g) : "memory");
}
__device__ __forceinline__ void cp_commit() {
    asm volatile("cp.async.commit_group;" ::: "memory");
}
__device__ __forceinline__ void cp_wait0() {
    asm volatile("cp.async.wait_group 0;" ::: "memory");
}
__device__ __forceinline__ void cp_wait1() {
    asm volatile("cp.async.wait_group 1;" ::: "memory");
}
__device__ __forceinline__ void ldmx4(uint32_t* r, uint32_t addr) {
    asm volatile("ldmatrix.sync.aligned.m8n8.x4.shared.b16 {%0,%1,%2,%3}, [%4];"
                 : "=r"(r[0]), "=r"(r[1]), "=r"(r[2]), "=r"(r[3]) : "r"(addr));
}
__device__ __forceinline__ void mma_f16(float* c, const uint32_t* a, const uint32_t* b) {
    asm volatile("mma.sync.aligned.m16n8k16.row.col.f32.f16.f16.f32 "
                 "{%0,%1,%2,%3},{%4,%5,%6,%7},{%8,%9},{%0,%1,%2,%3};"
                 : "+f"(c[0]), "+f"(c[1]), "+f"(c[2]), "+f"(c[3])
                 : "r"(a[0]), "r"(a[1]), "r"(a[2]), "r"(a[3]), "r"(b[0]), "r"(b[1]));
}

// ---------------- hi/lo fp16 split (activations) ----------------
__global__ __launch_bounds__(256)
void split_half_kernel(const float* __restrict__ in,
                       __half* __restrict__ hi, __half* __restrict__ lo, int n4)
{
    int i = blockIdx.x * 256 + threadIdx.x;
    if (i >= n4) return;
    float4 v = reinterpret_cast<const float4*>(in)[i];
    __half2 h01 = __floats2half2_rn(v.x, v.y);
    __half2 h23 = __floats2half2_rn(v.z, v.w);
    float2 f01 = __half22float2(h01);
    float2 f23 = __half22float2(h23);
    __half2 l01 = __floats2half2_rn(v.x - f01.x, v.y - f01.y);
    __half2 l23 = __floats2half2_rn(v.z - f23.x, v.w - f23.y);
    reinterpret_cast<__half2*>(hi)[2 * i + 0] = h01;
    reinterpret_cast<__half2*>(hi)[2 * i + 1] = h23;
    reinterpret_cast<__half2*>(lo)[2 * i + 0] = l01;
    reinterpret_cast<__half2*>(lo)[2 * i + 1] = l23;
}

// ---------------- fp16 convert for all 4 weights (one launch) ----------------
__global__ __launch_bounds__(256)
void conv_w_kernel(const float* __restrict__ Wq, const float* __restrict__ Wk,
                   const float* __restrict__ Wv, const float* __restrict__ Wo,
                   __half* __restrict__ dst)
{
    const int wsel = blockIdx.y;
    const float* src = (wsel == 0) ? Wq : (wsel == 1) ? Wk : (wsel == 2) ? Wv : Wo;
    int i = blockIdx.x * 256 + threadIdx.x;         // float4 index within weight
    float4 v = reinterpret_cast<const float4*>(src)[i];
    __half2* o = reinterpret_cast<__half2*>(dst + (size_t)wsel * EMB * EMB);
    o[2 * i + 0] = __floats2half2_rn(v.x, v.y);
    o[2 * i + 1] = __floats2half2_rn(v.z, v.w);
}

// ---------------- mma.sync fp16 2-pass GEMM: C[M,N] = act( A @ W^T ) ----------------
// Tile 128x128, BK=64 fp16, 8 warps (4m x 2n), warp tile 32x64.
// Smem rows padded to 72 halves (144 B) -> ldmatrix conflict-free.
// Stage = { A_hi, A_lo, B } tiles; double-buffered via cp.async.
// MODE 0: fused QKV (gridDim.z=3 selects weight+output; z<2 -> elu+1)
// MODE 1: output projection (+bias)
#define KC        64
#define NKC       (EMB / KC)            // 16
#define ROW_HALF  72                    // halves per smem row (64 + 8 pad)
#define ROW_B     (ROW_HALF * 2)        // 144 bytes
#define TILE_BY   (128 * ROW_B)         // 18432
#define STAGE_BY  (3 * TILE_BY)         // 55296 (Ah, Al, B)
#define GEMM_SMEM (2 * STAGE_BY)        // 110592

template <int MODE>
__global__ __launch_bounds__(256, 2)
void mma_gemm_half(const __half* __restrict__ Ah, const __half* __restrict__ Al,
                   const __half* __restrict__ Wall, const float* __restrict__ bias,
                   float* __restrict__ Cq, float* __restrict__ Ck, float* __restrict__ Cv)
{
    extern __shared__ char smem[];
    const uint32_t sb = smem_u32(smem);

    const int z = (MODE == 0) ? blockIdx.z : 0;
    const __half* B = Wall + (size_t)z * EMB * EMB;
    float* C = (MODE == 1) ? Cq : (z == 0) ? Cq : (z == 1) ? Ck : Cv;
    const int do_phi = (MODE == 0) && (z < 2);

    const int tid = threadIdx.x;
    const int wid = tid >> 5;
    const int lid = tid & 31;
    const int bm  = blockIdx.y * 128;
    const int bn  = blockIdx.x * 128;

    const int m_off = (wid & 3) * 32;
    const int n_off = (wid >> 2) * 64;

    // ldmatrix per-lane address components
    const int q   = lid >> 3;
    const int a_r = ((q & 1) << 3) + (lid & 7);
    const int a_c = (q >> 1) << 3;
    const int b_r = ((q >> 1) << 3) + (lid & 7);
    const int b_c = (q & 1) << 3;

    // cp.async mapping: 3 tiles x 1024 16B-vectors = 12 per thread per chunk
    auto load_chunk = [&](int kc, int stg) {
#pragma unroll
        for (int it = 0; it < 12; it++) {
            int idx = tid + it * 256;
            int t = idx >> 10;                 // 0:Ah 1:Al 2:B
            int r = (idx >> 3) & 127;
            int c = idx & 7;
            uint32_t saddr = sb + stg * STAGE_BY + t * TILE_BY + r * ROW_B + c * 16;
            const __half* src = (t == 0) ? Ah : (t == 1) ? Al : B;
            int grow = (t < 2) ? (bm + r) : (bn + r);
            cp16(saddr, src + (size_t)grow * EMB + kc * KC + c * 8);
        }
        cp_commit();
    };

    float acc[2][8][4];
#pragma unroll
    for (int mt = 0; mt < 2; mt++)
#pragma unroll
        for (int nt = 0; nt < 8; nt++)
#pragma unroll
            for (int e = 0; e < 4; e++) acc[mt][nt][e] = 0.f;

    load_chunk(0, 0);

    for (int kc = 0; kc < NKC; kc++) {
        if (kc + 1 < NKC) { load_chunk(kc + 1, (kc + 1) & 1); cp_wait1(); }
        else              { cp_wait0(); }
        __syncthreads();

        const uint32_t uAh = sb + (kc & 1) * STAGE_BY;
        const uint32_t uAl = uAh + TILE_BY;
        const uint32_t uB  = uAl + TILE_BY;

#pragma unroll
        for (int ks = 0; ks < 4; ks++) {
            const int kcol2 = ks * 32;         // 16 halves = 32 bytes

            uint32_t bf[4][4];
#pragma unroll
            for (int p = 0; p < 4; p++)
                ldmx4(bf[p], uB + (n_off + p * 16 + b_r) * ROW_B + kcol2 + b_c * 2);

            uint32_t af[2][4];
#pragma unroll
            for (int mt = 0; mt < 2; mt++)
                ldmx4(af[mt], uAh + (m_off + mt * 16 + a_r) * ROW_B + kcol2 + a_c * 2);
#pragma unroll
            for (int mt = 0; mt < 2; mt++)
#pragma unroll
                for (int nt = 0; nt < 8; nt++)
                    mma_f16(acc[mt][nt], af[mt], &bf[nt >> 1][(nt & 1) * 2]);

#pragma unroll
            for (int mt = 0; mt < 2; mt++)
                ldmx4(af[mt], uAl + (m_off + mt * 16 + a_r) * ROW_B + kcol2 + a_c * 2);
#pragma unroll
            for (int mt = 0; mt < 2; mt++)
#pragma unroll
                for (int nt = 0; nt < 8; nt++)
                    mma_f16(acc[mt][nt], af[mt], &bf[nt >> 1][(nt & 1) * 2]);
        }
        __syncthreads();
    }

    // Epilogue: direct global float2 stores
    const int gr  = lid >> 2;
    const int gc2 = (lid & 3) * 2;
#pragma unroll
    for (int mt = 0; mt < 2; mt++) {
#pragma unroll
        for (int nt = 0; nt < 8; nt++) {
            int row0 = bm + m_off + mt * 16 + gr;
            int col  = bn + n_off + nt * 8 + gc2;
            float2 v0 = make_float2(acc[mt][nt][0], acc[mt][nt][1]);
            float2 v1 = make_float2(acc[mt][nt][2], acc[mt][nt][3]);
            if (MODE == 0) {
                if (do_phi) {
                    v0.x = (v0.x > 0.f) ? (v0.x + 1.f) : expf(v0.x);
                    v0.y = (v0.y > 0.f) ? (v0.y + 1.f) : expf(v0.y);
                    v1.x = (v1.x > 0.f) ? (v1.x + 1.f) : expf(v1.x);
                    v1.y = (v1.y > 0.f) ? (v1.y + 1.f) : expf(v1.y);
                }
            } else {
                float2 bv = *reinterpret_cast<const float2*>(bias + col);
                v0.x += bv.x; v0.y += bv.y;
                v1.x += bv.x; v1.y += bv.y;
            }
            *reinterpret_cast<float2*>(C + (size_t)row0 * EMB + col)       = v0;
            *reinterpret_cast<float2*>(C + (size_t)(row0 + 8) * EMB + col) = v1;
        }
    }
}

// ---------------- Phase A: per-chunk stats  S_c = k^T v,  z_c = sum_j k ----------------
__global__ __launch_bounds__(256)
void chunk_stats_kernel(const float* __restrict__ K, const float* __restrict__ V,
                        float* __restrict__ gS, float* __restrict__ gZ)
{
    __shared__ float Ks[CHK][HD];
    __shared__ float Vs[CHK][HD];

    const int blk = blockIdx.x;
    const int c   = blk % NC;
    const int bh  = blk / NC;
    const int b   = bh / NH;
    const int h   = bh % NH;
    const int tid = threadIdx.x;

    const size_t base = ((size_t)(b * TSEQ) + (size_t)c * CHK) * EMB + (size_t)h * HD;

#pragma unroll
    for (int it = 0; it < 8; it++) {
        int idx = tid + it * 256;
        int r = idx >> 4, q4 = (idx & 15) * 4;
        *(float4*)&Ks[r][q4] = *(const float4*)(K + base + (size_t)r * EMB + q4);
        *(float4*)&Vs[r][q4] = *(const float4*)(V + base + (size_t)r * EMB + q4);
    }
    __syncthreads();

    const int tx = tid & 15, ty = tid >> 4;
    float acc[4][4];
#pragma unroll
    for (int i = 0; i < 4; i++)
#pragma unroll
        for (int e = 0; e < 4; e++) acc[i][e] = 0.f;

    for (int j = 0; j < CHK; j++) {
        float rk[4], rv[4];
#pragma unroll
        for (int i = 0; i < 4; i++) rk[i] = Ks[j][ty * 4 + i];
#pragma unroll
        for (int e = 0; e < 4; e++) rv[e] = Vs[j][tx * 4 + e];
#pragma unroll
        for (int i = 0; i < 4; i++)
#pragma unroll
            for (int e = 0; e < 4; e++)
                acc[i][e] = fmaf(rk[i], rv[e], acc[i][e]);
    }

    float* Sout = gS + (size_t)blk * (HD * HD);
#pragma unroll
    for (int i = 0; i < 4; i++)
#pragma unroll
        for (int e = 0; e < 4; e++)
            Sout[(ty * 4 + i) * HD + tx * 4 + e] = acc[i][e];

    if (tid < HD) {
        float z = 0.f;
        for (int j = 0; j < CHK; j++) z += Ks[j][tid];
        gZ[(size_t)blk * HD + tid] = z;
    }
}

// ---------------- Phase B: exclusive prefix over chunks ----------------
__global__ __launch_bounds__(256)
void prefix_kernel(const float* __restrict__ gS, const float* __restrict__ gZ,
                   float* __restrict__ gSp, float* __restrict__ gZp)
{
    const int bh  = blockIdx.x;
    const int tid = threadIdx.x;

    float acc[16];
#pragma unroll
    for (int i = 0; i < 16; i++) acc[i] = 0.f;

    for (int c = 0; c < NC; c++) {
        size_t off = ((size_t)bh * NC + c) * (HD * HD);
#pragma unroll
        for (int i = 0; i < 16; i++) {
            gSp[off + tid * 16 + i] = acc[i];
            acc[i] += gS[off + tid * 16 + i];
        }
    }
    if (tid < HD) {
        float z = 0.f;
        for (int c = 0; c < NC; c++) {
            size_t off = ((size_t)bh * NC + c) * HD;
            gZp[off + tid] = z;
            z += gZ[off + tid];
        }
    }
}

// ---------------- Phase C: per-chunk output ----------------
#define SM_QT   0
#define SM_KT   (SM_QT + 64 * 128)
#define SM_AS   (SM_KT + 64 * 128)
#define SM_SS   (SM_AS + 128 * 129)
#define SM_ZC   (SM_SS + 64 * 64)
#define SM_RSP  (SM_ZC + 64)
#define SM_DEN  (SM_RSP + 128 * 17)
#define SM_TOT  (SM_DEN + 128)
#define SMEM_BYTES_C (SM_TOT * 4)

__global__ __launch_bounds__(256)
void attn_out_kernel(const float* __restrict__ Q, const float* __restrict__ K,
                     const float* __restrict__ V,
                     const float* __restrict__ gSp, const float* __restrict__ gZp,
                     float* __restrict__ Aout)
{
    extern __shared__ float sm[];
    float* Qt  = sm + SM_QT;
    float* Kt  = sm + SM_KT;
    float* As  = sm + SM_AS;
    float* Ss  = sm + SM_SS;
    float* zc  = sm + SM_ZC;
    float* rsP = sm + SM_RSP;
    float* den = sm + SM_DEN;

    const int blk = blockIdx.x;
    const int c   = blk % NC;
    const int bh  = blk / NC;
    const int b   = bh / NH;
    const int h   = bh % NH;
    const int tid = threadIdx.x;

    const size_t base = ((size_t)(b * TSEQ) + (size_t)c * CHK) * EMB + (size_t)h * HD;

#pragma unroll
    for (int it = 0; it < 8; it++) {
        int idx = tid + it * 256;
        int r = idx >> 4, q4 = (idx & 15) * 4;
        float4 vq = *(const float4*)(Q + base + (size_t)r * EMB + q4);
        Qt[(q4 + 0) * 128 + r] = vq.x; Qt[(q4 + 1) * 128 + r] = vq.y;
        Qt[(q4 + 2) * 128 + r] = vq.z; Qt[(q4 + 3) * 128 + r] = vq.w;
        float4 vk = *(const float4*)(K + base + (size_t)r * EMB + q4);
        Kt[(q4 + 0) * 128 + r] = vk.x; Kt[(q4 + 1) * 128 + r] = vk.y;
        Kt[(q4 + 2) * 128 + r] = vk.z; Kt[(q4 + 3) * 128 + r] = vk.w;
    }
    {
        size_t soff = (size_t)blk * (HD * HD);
#pragma unroll
        for (int it = 0; it < 4; it++) {
            int idx = tid + it * 256;
            *(float4*)&Ss[idx * 4] = *(const float4*)(gSp + soff + idx * 4);
        }
        if (tid < HD) zc[tid] = gZp[(size_t)blk * HD + tid];
    }
    __syncthreads();

    const int tx = tid & 15, ty = tid >> 4;

    {
        float a[8][8];
#pragma unroll
        for (int i = 0; i < 8; i++)
#pragma unroll
            for (int j = 0; j < 8; j++) a[i][j] = 0.f;

        for (int dd = 0; dd < HD; dd++) {
            float rq[8], rk[8];
#pragma unroll
            for (int i = 0; i < 8; i++) rq[i] = Qt[dd * 128 + ty * 8 + i];
#pragma unroll
            for (int j = 0; j < 8; j++) rk[j] = Kt[dd * 128 + tx * 8 + j];
#pragma unroll
            for (int i = 0; i < 8; i++)
#pragma unroll
                for (int j = 0; j < 8; j++)
                    a[i][j] = fmaf(rq[i], rk[j], a[i][j]);
        }
#pragma unroll
        for (int i = 0; i < 8; i++) {
            int row = ty * 8 + i;
            float rsum = 0.f;
#pragma unroll
            for (int j = 0; j < 8; j++) {
                int col = tx * 8 + j;
                float v = (col <= row) ? a[i][j] : 0.f;
                As[row * 129 + col] = v;
                rsum += v;
            }
            rsP[row * 17 + tx] = rsum;
        }
    }
    __syncthreads();

    float* Vs = Kt;
#pragma unroll
    for (int it = 0; it < 8; it++) {
        int idx = tid + it * 256;
        int r = idx >> 4, q4 = (idx & 15) * 4;
        *(float4*)&Vs[r * 64 + q4] = *(const float4*)(V + base + (size_t)r * EMB + q4);
    }
    if (tid < CHK) {
        float rs = 0.f;
#pragma unroll
        for (int p = 0; p < 16; p++) rs += rsP[tid * 17 + p];
        float qz = 0.f;
        for (int dd = 0; dd < HD; dd++) qz += Qt[dd * 128 + tid] * zc[dd];
        den[tid] = rs + qz + EPS_F;
    }
    __syncthreads();

    float num[8][4];
#pragma unroll
    for (int i = 0; i < 8; i++)
#pragma unroll
        for (int e = 0; e < 4; e++) num[i][e] = 0.f;

    for (int j = 0; j < CHK; j++) {
        float ra[8], rv[4];
#pragma unroll
        for (int i = 0; i < 8; i++) ra[i] = As[(ty * 8 + i) * 129 + j];
#pragma unroll
        for (int e = 0; e < 4; e++) rv[e] = Vs[j * 64 + tx * 4 + e];
#pragma unroll
        for (int i = 0; i < 8; i++)
#pragma unroll
            for (int e = 0; e < 4; e++)
                num[i][e] = fmaf(ra[i], rv[e], num[i][e]);
    }
    for (int dd = 0; dd < HD; dd++) {
        float rq[8], rs2[4];
#pragma unroll
        for (int i = 0; i < 8; i++) rq[i] = Qt[dd * 128 + ty * 8 + i];
#pragma unroll
        for (int e = 0; e < 4; e++) rs2[e] = Ss[dd * 64 + tx * 4 + e];
#pragma unroll
        for (int i = 0; i < 8; i++)
#pragma unroll
            for (int e = 0; e < 4; e++)
                num[i][e] = fmaf(rq[i], rs2[e], num[i][e]);
    }

#pragma unroll
    for (int i = 0; i < 8; i++) {
        int row = ty * 8 + i;
        float inv = 1.f / den[row];
#pragma unroll
        for (int e = 0; e < 4; e++) {
            int col = tx * 4 + e;
            Aout[base + (size_t)row * EMB + col] = num[i][e] * inv;
        }
    }
}

// ---------------- launch ----------------
extern "C" void kernel_launch(void* const* d_in, const int* in_sizes, int n_in,
                              void* d_out, int out_size)
{
    const float* x  = (const float*)d_in[0];
    const float* Wq = (const float*)d_in[1];
    const float* Wk = (const float*)d_in[2];
    const float* Wv = (const float*)d_in[3];
    const float* Wo = (const float*)d_in[4];
    const float* bo = (const float*)d_in[5];
    float* out = (float*)d_out;
    (void)in_sizes; (void)n_in; (void)out_size;

    float *pQ, *pK, *pV, *pA, *pS, *pSp, *pZ, *pZp;
    cudaGetSymbolAddress((void**)&pQ,  g_Q);
    cudaGetSymbolAddress((void**)&pK,  g_K);
    cudaGetSymbolAddress((void**)&pV,  g_V);
    cudaGetSymbolAddress((void**)&pA,  g_attn);
    cudaGetSymbolAddress((void**)&pS,  g_S);
    cudaGetSymbolAddress((void**)&pSp, g_Sp);
    cudaGetSymbolAddress((void**)&pZ,  g_z);
    cudaGetSymbolAddress((void**)&pZp, g_zp);

    __half *xh, *xl, *ah, *al, *wh;
    cudaGetSymbolAddress((void**)&xh, g_xh);
    cudaGetSymbolAddress((void**)&xl, g_xl);
    cudaGetSymbolAddress((void**)&ah, g_ah);
    cudaGetSymbolAddress((void**)&al, g_al);
    cudaGetSymbolAddress((void**)&wh, g_w);

    cudaFuncSetAttribute(attn_out_kernel,
                         cudaFuncAttributeMaxDynamicSharedMemorySize, SMEM_BYTES_C);
    cudaFuncSetAttribute(mma_gemm_half<0>,
                         cudaFuncAttributeMaxDynamicSharedMemorySize, GEMM_SMEM);
    cudaFuncSetAttribute(mma_gemm_half<1>,
                         cudaFuncAttributeMaxDynamicSharedMemorySize, GEMM_SMEM);

    const int n4x = MROWS * EMB / 4;   // 1048576
    const int n4w = EMB * EMB / 4;     // 262144

    // operand conversion
    split_half_kernel<<<n4x / 256, 256>>>(x, xh, xl, n4x);
    conv_w_kernel<<<dim3(n4w / 256, 4), 256>>>(Wq, Wk, Wv, Wo, wh);

    // Fused Q/K/V projections (z selects weight; phi fused for z<2)
    dim3 qkv_grid(EMB / 128, MROWS / 128, 3);     // (8, 32, 3)
    mma_gemm_half<0><<<qkv_grid, 256, GEMM_SMEM>>>(xh, xl, wh, nullptr, pQ, pK, pV);

    // Chunked recurrent state: stats -> prefix -> output
    chunk_stats_kernel<<<BATCH * NH * NC, 256>>>(pK, pV, pS, pZ);
    prefix_kernel<<<BATCH * NH, 256>>>(pS, pZ, pSp, pZp);
    attn_out_kernel<<<BATCH * NH * NC, 256, SMEM_BYTES_C>>>(pQ, pK, pV, pSp, pZp, pA);

    // Output projection + bias
    split_half_kernel<<<n4x / 256, 256>>>(pA, ah, al, n4x);
    dim3 o_grid(EMB / 128, MROWS / 128, 1);
    mma_gemm_half<1><<<o_grid, 256, GEMM_SMEM>>>(ah, al, wh + (size_t)3 * EMB * EMB, bo,
                                                 out, nullptr, nullptr);
}

// round 11
// speedup vs baseline: 3.4691x; 1.1631x over previous
#include <cuda_runtime.h>
#include <cuda_fp16.h>
#include <cstdint>
#include <cstddef>

// Problem constants (fixed by setup_inputs)
#define BATCH 2
#define TSEQ  2048
#define EMB   1024
#define NH    16
#define HD    64
#define CHK   128
#define NC    (TSEQ / CHK)          // 16
#define MROWS (BATCH * TSEQ)        // 4096
#define EPS_F 1e-5f

// ---------------- scratch (static device allocations) ----------------
__device__ float g_Q[(size_t)MROWS * EMB];
__device__ float g_K[(size_t)MROWS * EMB];
__device__ float g_V[(size_t)MROWS * EMB];
__device__ float g_S [(size_t)BATCH * NH * NC * HD * HD];   // per-chunk  k^T v
__device__ float g_Sp[(size_t)BATCH * NH * NC * HD * HD];   // exclusive prefix
__device__ float g_z [(size_t)BATCH * NH * NC * HD];
__device__ float g_zp[(size_t)BATCH * NH * NC * HD];

// fp16 operands for tensor-core GEMMs
__device__ __half g_xh[(size_t)MROWS * EMB];
__device__ __half g_xl[(size_t)MROWS * EMB];
__device__ __half g_ah[(size_t)MROWS * EMB];   // attn output hi (written by attn kernel)
__device__ __half g_al[(size_t)MROWS * EMB];   // attn output lo
__device__ __half g_w [(size_t)4 * EMB * EMB]; // Wq, Wk, Wv, Wo (fp16)

// ---------------- PTX helpers (arch-agnostic: valid on target sm_103) ----------------
__device__ __forceinline__ uint32_t smem_u32(const void* p) {
    uint32_t a;
    asm("{ .reg .u64 t; cvta.to.shared.u64 t, %1; cvt.u32.u64 %0, t; }"
        : "=r"(a) : "l"(p));
    return a;
}
__device__ __forceinline__ void cp16(uint32_t s, const void* g) {
    asm volatile("cp.async.cg.shared.global [%0], [%1], 16;" :: "r"(s), "l"(g) : "memory");
}
__device__ __forceinline__ void cp_commit() {
    asm volatile("cp.async.commit_group;" ::: "memory");
}
__device__ __forceinline__ void cp_wait0() {
    asm volatile("cp.async.wait_group 0;" ::: "memory");
}
__device__ __forceinline__ void cp_wait1() {
    asm volatile("cp.async.wait_group 1;" ::: "memory");
}
__device__ __forceinline__ void ldmx4(uint32_t* r, uint32_t addr) {
    asm volatile("ldmatrix.sync.aligned.m8n8.x4.shared.b16 {%0,%1,%2,%3}, [%4];"
                 : "=r"(r[0]), "=r"(r[1]), "=r"(r[2]), "=r"(r[3]) : "r"(addr));
}
__device__ __forceinline__ void mma_f16(float* c, const uint32_t* a, const uint32_t* b) {
    asm volatile("mma.sync.aligned.m16n8k16.row.col.f32.f16.f16.f32 "
                 "{%0,%1,%2,%3},{%4,%5,%6,%7},{%8,%9},{%0,%1,%2,%3};"
                 : "+f"(c[0]), "+f"(c[1]), "+f"(c[2]), "+f"(c[3])
                 : "r"(a[0]), "r"(a[1]), "r"(a[2]), "r"(a[3]), "r"(b[0]), "r"(b[1]));
}

// ---------------- hi/lo fp16 split (x only) ----------------
__global__ __launch_bounds__(256)
void split_half_kernel(const float* __restrict__ in,
                       __half* __restrict__ hi, __half* __restrict__ lo, int n4)
{
    int i = blockIdx.x * 256 + threadIdx.x;
    if (i >= n4) return;
    float4 v = reinterpret_cast<const float4*>(in)[i];
    __half2 h01 = __floats2half2_rn(v.x, v.y);
    __half2 h23 = __floats2half2_rn(v.z, v.w);
    float2 f01 = __half22float2(h01);
    float2 f23 = __half22float2(h23);
    __half2 l01 = __floats2half2_rn(v.x - f01.x, v.y - f01.y);
    __half2 l23 = __floats2half2_rn(v.z - f23.x, v.w - f23.y);
    reinterpret_cast<__half2*>(hi)[2 * i + 0] = h01;
    reinterpret_cast<__half2*>(hi)[2 * i + 1] = h23;
    reinterpret_cast<__half2*>(lo)[2 * i + 0] = l01;
    reinterpret_cast<__half2*>(lo)[2 * i + 1] = l23;
}

// ---------------- fp16 convert for all 4 weights (one launch) ----------------
__global__ __launch_bounds__(256)
void conv_w_kernel(const float* __restrict__ Wq, const float* __restrict__ Wk,
                   const float* __restrict__ Wv, const float* __restrict__ Wo,
                   __half* __restrict__ dst)
{
    const int wsel = blockIdx.y;
    const float* src = (wsel == 0) ? Wq : (wsel == 1) ? Wk : (wsel == 2) ? Wv : Wo;
    int i = blockIdx.x * 256 + threadIdx.x;
    float4 v = reinterpret_cast<const float4*>(src)[i];
    __half2* o = reinterpret_cast<__half2*>(dst + (size_t)wsel * EMB * EMB);
    o[2 * i + 0] = __floats2half2_rn(v.x, v.y);
    o[2 * i + 1] = __floats2half2_rn(v.z, v.w);
}

// ---------------- mma.sync fp16 2-pass GEMM: C[M,N] = act( A @ W^T ) ----------------
#define KC        64
#define NKC       (EMB / KC)            // 16
#define ROW_HALF  72
#define ROW_B     (ROW_HALF * 2)        // 144
#define TILE_BY   (128 * ROW_B)         // 18432
#define STAGE_BY  (3 * TILE_BY)         // 55296
#define GEMM_SMEM (2 * STAGE_BY)        // 110592

template <int MODE>
__global__ __launch_bounds__(256, 2)
void mma_gemm_half(const __half* __restrict__ Ah, const __half* __restrict__ Al,
                   const __half* __restrict__ Wall, const float* __restrict__ bias,
                   float* __restrict__ Cq, float* __restrict__ Ck, float* __restrict__ Cv)
{
    extern __shared__ char smem[];
    const uint32_t sb = smem_u32(smem);

    const int z = (MODE == 0) ? blockIdx.z : 0;
    const __half* B = Wall + (size_t)z * EMB * EMB;
    float* C = (MODE == 1) ? Cq : (z == 0) ? Cq : (z == 1) ? Ck : Cv;
    const int do_phi = (MODE == 0) && (z < 2);

    const int tid = threadIdx.x;
    const int wid = tid >> 5;
    const int lid = tid & 31;
    const int bm  = blockIdx.y * 128;
    const int bn  = blockIdx.x * 128;

    const int m_off = (wid & 3) * 32;
    const int n_off = (wid >> 2) * 64;

    const int q   = lid >> 3;
    const int a_r = ((q & 1) << 3) + (lid & 7);
    const int a_c = (q >> 1) << 3;
    const int b_r = ((q >> 1) << 3) + (lid & 7);
    const int b_c = (q & 1) << 3;

    auto load_chunk = [&](int kc, int stg) {
#pragma unroll
        for (int it = 0; it < 12; it++) {
            int idx = tid + it * 256;
            int t = idx >> 10;
            int r = (idx >> 3) & 127;
            int c = idx & 7;
            uint32_t saddr = sb + stg * STAGE_BY + t * TILE_BY + r * ROW_B + c * 16;
            const __half* src = (t == 0) ? Ah : (t == 1) ? Al : B;
            int grow = (t < 2) ? (bm + r) : (bn + r);
            cp16(saddr, src + (size_t)grow * EMB + kc * KC + c * 8);
        }
        cp_commit();
    };

    float acc[2][8][4];
#pragma unroll
    for (int mt = 0; mt < 2; mt++)
#pragma unroll
        for (int nt = 0; nt < 8; nt++)
#pragma unroll
            for (int e = 0; e < 4; e++) acc[mt][nt][e] = 0.f;

    load_chunk(0, 0);

    for (int kc = 0; kc < NKC; kc++) {
        if (kc + 1 < NKC) { load_chunk(kc + 1, (kc + 1) & 1); cp_wait1(); }
        else              { cp_wait0(); }
        __syncthreads();

        const uint32_t uAh = sb + (kc & 1) * STAGE_BY;
        const uint32_t uAl = uAh + TILE_BY;
        const uint32_t uB  = uAl + TILE_BY;

#pragma unroll
        for (int ks = 0; ks < 4; ks++) {
            const int kcol2 = ks * 32;

            uint32_t bf[4][4];
#pragma unroll
            for (int p = 0; p < 4; p++)
                ldmx4(bf[p], uB + (n_off + p * 16 + b_r) * ROW_B + kcol2 + b_c * 2);

            uint32_t af[2][4];
#pragma unroll
            for (int mt = 0; mt < 2; mt++)
                ldmx4(af[mt], uAh + (m_off + mt * 16 + a_r) * ROW_B + kcol2 + a_c * 2);
#pragma unroll
            for (int mt = 0; mt < 2; mt++)
#pragma unroll
                for (int nt = 0; nt < 8; nt++)
                    mma_f16(acc[mt][nt], af[mt], &bf[nt >> 1][(nt & 1) * 2]);

#pragma unroll
            for (int mt = 0; mt < 2; mt++)
                ldmx4(af[mt], uAl + (m_off + mt * 16 + a_r) * ROW_B + kcol2 + a_c * 2);
#pragma unroll
            for (int mt = 0; mt < 2; mt++)
#pragma unroll
                for (int nt = 0; nt < 8; nt++)
                    mma_f16(acc[mt][nt], af[mt], &bf[nt >> 1][(nt & 1) * 2]);
        }
        __syncthreads();
    }

    const int gr  = lid >> 2;
    const int gc2 = (lid & 3) * 2;
#pragma unroll
    for (int mt = 0; mt < 2; mt++) {
#pragma unroll
        for (int nt = 0; nt < 8; nt++) {
            int row0 = bm + m_off + mt * 16 + gr;
            int col  = bn + n_off + nt * 8 + gc2;
            float2 v0 = make_float2(acc[mt][nt][0], acc[mt][nt][1]);
            float2 v1 = make_float2(acc[mt][nt][2], acc[mt][nt][3]);
            if (MODE == 0) {
                if (do_phi) {
                    v0.x = (v0.x > 0.f) ? (v0.x + 1.f) : expf(v0.x);
                    v0.y = (v0.y > 0.f) ? (v0.y + 1.f) : expf(v0.y);
                    v1.x = (v1.x > 0.f) ? (v1.x + 1.f) : expf(v1.x);
                    v1.y = (v1.y > 0.f) ? (v1.y + 1.f) : expf(v1.y);
                }
            } else {
                float2 bv = *reinterpret_cast<const float2*>(bias + col);
                v0.x += bv.x; v0.y += bv.y;
                v1.x += bv.x; v1.y += bv.y;
            }
            *reinterpret_cast<float2*>(C + (size_t)row0 * EMB + col)       = v0;
            *reinterpret_cast<float2*>(C + (size_t)(row0 + 8) * EMB + col) = v1;
        }
    }
}

// ---------------- Phase A: per-chunk stats  S_c = k^T v,  z_c = sum_j k ----------------
__global__ __launch_bounds__(256)
void chunk_stats_kernel(const float* __restrict__ K, const float* __restrict__ V,
                        float* __restrict__ gS, float* __restrict__ gZ)
{
    __shared__ float Ks[CHK][HD];
    __shared__ float Vs[CHK][HD];

    const int blk = blockIdx.x;
    const int c   = blk % NC;
    const int bh  = blk / NC;
    const int b   = bh / NH;
    const int h   = bh % NH;
    const int tid = threadIdx.x;

    const size_t base = ((size_t)(b * TSEQ) + (size_t)c * CHK) * EMB + (size_t)h * HD;

#pragma unroll
    for (int it = 0; it < 8; it++) {
        int idx = tid + it * 256;
        int r = idx >> 4, q4 = (idx & 15) * 4;
        *(float4*)&Ks[r][q4] = *(const float4*)(K + base + (size_t)r * EMB + q4);
        *(float4*)&Vs[r][q4] = *(const float4*)(V + base + (size_t)r * EMB + q4);
    }
    __syncthreads();

    const int tx = tid & 15, ty = tid >> 4;
    float acc[4][4];
#pragma unroll
    for (int i = 0; i < 4; i++)
#pragma unroll
        for (int e = 0; e < 4; e++) acc[i][e] = 0.f;

    for (int j = 0; j < CHK; j++) {
        float rk[4], rv[4];
#pragma unroll
        for (int i = 0; i < 4; i++) rk[i] = Ks[j][ty * 4 + i];
#pragma unroll
        for (int e = 0; e < 4; e++) rv[e] = Vs[j][tx * 4 + e];
#pragma unroll
        for (int i = 0; i < 4; i++)
#pragma unroll
            for (int e = 0; e < 4; e++)
                acc[i][e] = fmaf(rk[i], rv[e], acc[i][e]);
    }

    float* Sout = gS + (size_t)blk * (HD * HD);
#pragma unroll
    for (int i = 0; i < 4; i++)
#pragma unroll
        for (int e = 0; e < 4; e++)
            Sout[(ty * 4 + i) * HD + tx * 4 + e] = acc[i][e];

    if (tid < HD) {
        float z = 0.f;
        for (int j = 0; j < CHK; j++) z += Ks[j][tid];
        gZ[(size_t)blk * HD + tid] = z;
    }
}

// ---------------- Phase B: exclusive prefix over chunks ----------------
__global__ __launch_bounds__(256)
void prefix_kernel(const float* __restrict__ gS, const float* __restrict__ gZ,
                   float* __restrict__ gSp, float* __restrict__ gZp)
{
    const int bh  = blockIdx.x;
    const int tid = threadIdx.x;

    float acc[16];
#pragma unroll
    for (int i = 0; i < 16; i++) acc[i] = 0.f;

    for (int c = 0; c < NC; c++) {
        size_t off = ((size_t)bh * NC + c) * (HD * HD);
#pragma unroll
        for (int i = 0; i < 16; i++) {
            gSp[off + tid * 16 + i] = acc[i];
            acc[i] += gS[off + tid * 16 + i];
        }
    }
    if (tid < HD) {
        float z = 0.f;
        for (int c = 0; c < NC; c++) {
            size_t off = ((size_t)bh * NC + c) * HD;
            gZp[off + tid] = z;
            z += gZ[off + tid];
        }
    }
}

// ---------------- Phase C: tensor-core per-chunk output ----------------
// out = ( A@v + q@Sp ) / ( rowsum(A) + q.zp + eps ),  A = (q k^T) masked
// All matmuls via mma.sync fp16, 3-pass hi/lo x hi/lo (error ~2^-22, fp32-class).
// Output written directly as fp16 hi/lo (g_ah / g_al) for the O projection.
#define QROW   72
#define QROWB  144
#define AROW   136
#define AROWB  272
#define OFF_QH   0
#define OFF_QL   18432
#define OFF_KH   36864
#define OFF_KL   55296
#define OFF_AH   73728
#define OFF_AL   108544
#define OFF_VTH  143360
#define OFF_VTL  160768
#define OFF_SPTH 178176
#define OFF_SPTL 187392
#define OFF_ZC   196608
#define OFF_DEN  196864
#define OFF_RSP  197376
#define ATTN_SMEM 198400

__global__ __launch_bounds__(256, 1)
void attn_mma_kernel(const float* __restrict__ Q, const float* __restrict__ K,
                     const float* __restrict__ V,
                     const float* __restrict__ gSp, const float* __restrict__ gZp,
                     __half* __restrict__ Oh, __half* __restrict__ Ol)
{
    extern __shared__ char smem[];
    const uint32_t sb = smem_u32(smem);

    const int blk = blockIdx.x;
    const int c   = blk % NC;
    const int bh  = blk / NC;
    const int b   = bh / NH;
    const int h   = bh % NH;
    const int tid = threadIdx.x;
    const int wid = tid >> 5;
    const int lid = tid & 31;

    const size_t base = ((size_t)(b * TSEQ) + (size_t)c * CHK) * EMB + (size_t)h * HD;

    float* zcs  = reinterpret_cast<float*>(smem + OFF_ZC);
    float* den  = reinterpret_cast<float*>(smem + OFF_DEN);
    float* rsP  = reinterpret_cast<float*>(smem + OFF_RSP);   // [128][2]

    // ---- P0: global fp32 -> smem fp16 hi/lo (q, k row-major; v, Sp transposed) ----
#pragma unroll
    for (int it = 0; it < 8; it++) {
        int idx = tid + it * 256;                 // 2048 float4 slots
        int r = idx >> 4, c4 = (idx & 15) * 4;
        {   // Q
            float4 v = *(const float4*)(Q + base + (size_t)r * EMB + c4);
            __half h0 = __float2half(v.x), h1 = __float2half(v.y);
            __half h2 = __float2half(v.z), h3 = __float2half(v.w);
            char* ph = smem + OFF_QH + r * QROWB + c4 * 2;
            char* pl = smem + OFF_QL + r * QROWB + c4 * 2;
            *(__half2*)(ph)     = __halves2half2(h0, h1);
            *(__half2*)(ph + 4) = __halves2half2(h2, h3);
            *(__half2*)(pl)     = __halves2half2(__float2half(v.x - __half2float(h0)),
                                                 __float2half(v.y - __half2float(h1)));
            *(__half2*)(pl + 4) = __halves2half2(__float2half(v.z - __half2float(h2)),
                                                 __float2half(v.w - __half2float(h3)));
        }
        {   // K
            float4 v = *(const float4*)(K + base + (size_t)r * EMB + c4);
            __half h0 = __float2half(v.x), h1 = __float2half(v.y);
            __half h2 = __float2half(v.z), h3 = __float2half(v.w);
            char* ph = smem + OFF_KH + r * QROWB + c4 * 2;
            char* pl = smem + OFF_KL + r * QROWB + c4 * 2;
            *(__half2*)(ph)     = __halves2half2(h0, h1);
            *(__half2*)(ph + 4) = __halves2half2(h2, h3);
            *(__half2*)(pl)     = __halves2half2(__float2half(v.x - __half2float(h0)),
                                                 __float2half(v.y - __half2float(h1)));
            *(__half2*)(pl + 4) = __halves2half2(__float2half(v.z - __half2float(h2)),
                                                 __float2half(v.w - __half2float(h3)));
        }
        {   // V -> transposed vT[e][j]
            float4 v = *(const float4*)(V + base + (size_t)r * EMB + c4);
            float vv[4] = {v.x, v.y, v.z, v.w};
#pragma unroll
            for (int i = 0; i < 4; i++) {
                __half hh = __float2half(vv[i]);
                __half ll = __float2half(vv[i] - __half2float(hh));
                *(__half*)(smem + OFF_VTH + (c4 + i) * AROWB + r * 2) = hh;
                *(__half*)(smem + OFF_VTL + (c4 + i) * AROWB + r * 2) = ll;
            }
        }
    }
    // Sp -> transposed SpT[e][d]
#pragma unroll
    for (int it = 0; it < 4; it++) {
        int idx = tid + it * 256;                 // 1024 float4 slots
        int d = idx >> 4, e4 = (idx & 15) * 4;
        float4 v = *(const float4*)(gSp + (size_t)blk * (HD * HD) + (size_t)d * HD + e4);
        float vv[4] = {v.x, v.y, v.z, v.w};
#pragma unroll
        for (int i = 0; i < 4; i++) {
            __half hh = __float2half(vv[i]);
            __half ll = __float2half(vv[i] - __half2float(hh));
            *(__half*)(smem + OFF_SPTH + (e4 + i) * QROWB + d * 2) = hh;
            *(__half*)(smem + OFF_SPTL + (e4 + i) * QROWB + d * 2) = ll;
        }
    }
    if (tid < HD) zcs[tid] = gZp[(size_t)blk * HD + tid];
    __syncthreads();

    // ldmatrix per-lane address components
    const int q   = lid >> 3;
    const int a_r = ((q & 1) << 3) + (lid & 7);
    const int a_c = (q >> 1) << 3;
    const int b_r = ((q >> 1) << 3) + (lid & 7);
    const int b_c = (q & 1) << 3;
    const int gr  = lid >> 2;
    const int gc2 = (lid & 3) * 2;

    // ---- P1: A = q k^T, 3-pass, warp tile 32x64 (4m x 2n warps) ----
    {
        const int m_off = (wid & 3) * 32;
        const int n_off = (wid >> 2) * 64;
        const int wn    = wid >> 2;

        float acc[2][8][4];
#pragma unroll
        for (int mt = 0; mt < 2; mt++)
#pragma unroll
            for (int nt = 0; nt < 8; nt++)
#pragma unroll
                for (int e = 0; e < 4; e++) acc[mt][nt][e] = 0.f;

#pragma unroll
        for (int ks = 0; ks < 4; ks++) {
            const int kcol = ks * 32;
            uint32_t bfh[4][4];
#pragma unroll
            for (int p = 0; p < 4; p++)
                ldmx4(bfh[p], sb + OFF_KH + (n_off + p * 16 + b_r) * QROWB + kcol + b_c * 2);
            uint32_t af[2][4];
#pragma unroll
            for (int mt = 0; mt < 2; mt++)
                ldmx4(af[mt], sb + OFF_QH + (m_off + mt * 16 + a_r) * QROWB + kcol + a_c * 2);
#pragma unroll
            for (int mt = 0; mt < 2; mt++)
#pragma unroll
                for (int nt = 0; nt < 8; nt++)
                    mma_f16(acc[mt][nt], af[mt], &bfh[nt >> 1][(nt & 1) * 2]);
            uint32_t bfl[4][4];
#pragma unroll
            for (int p = 0; p < 4; p++)
                ldmx4(bfl[p], sb + OFF_KL + (n_off + p * 16 + b_r) * QROWB + kcol + b_c * 2);
#pragma unroll
            for (int mt = 0; mt < 2; mt++)
#pragma unroll
                for (int nt = 0; nt < 8; nt++)
                    mma_f16(acc[mt][nt], af[mt], &bfl[nt >> 1][(nt & 1) * 2]);
#pragma unroll
            for (int mt = 0; mt < 2; mt++)
                ldmx4(af[mt], sb + OFF_QL + (m_off + mt * 16 + a_r) * QROWB + kcol + a_c * 2);
#pragma unroll
            for (int mt = 0; mt < 2; mt++)
#pragma unroll
                for (int nt = 0; nt < 8; nt++)
                    mma_f16(acc[mt][nt], af[mt], &bfh[nt >> 1][(nt & 1) * 2]);
        }

        // mask + rowsum + hi/lo store of A
#pragma unroll
        for (int mt = 0; mt < 2; mt++) {
            const int r0 = m_off + mt * 16 + gr;
            const int r1 = r0 + 8;
            float s0 = 0.f, s1 = 0.f;
#pragma unroll
            for (int nt = 0; nt < 8; nt++) {
                const int col = n_off + nt * 8 + gc2;
                float c0 = (col     <= r0) ? acc[mt][nt][0] : 0.f;
                float c1 = (col + 1 <= r0) ? acc[mt][nt][1] : 0.f;
                float c2 = (col     <= r1) ? acc[mt][nt][2] : 0.f;
                float c3 = (col + 1 <= r1) ? acc[mt][nt][3] : 0.f;
                s0 += c0 + c1;
                s1 += c2 + c3;
                __half h0 = __float2half(c0), h1 = __float2half(c1);
                __half h2 = __float2half(c2), h3 = __float2half(c3);
                *(__half2*)(smem + OFF_AH + r0 * AROWB + col * 2) = __halves2half2(h0, h1);
                *(__half2*)(smem + OFF_AH + r1 * AROWB + col * 2) = __halves2half2(h2, h3);
                *(__half2*)(smem + OFF_AL + r0 * AROWB + col * 2) =
                    __halves2half2(__float2half(c0 - __half2float(h0)),
                                   __float2half(c1 - __half2float(h1)));
                *(__half2*)(smem + OFF_AL + r1 * AROWB + col * 2) =
                    __halves2half2(__float2half(c2 - __half2float(h2)),
                                   __float2half(c3 - __half2float(h3)));
            }
            s0 += __shfl_xor_sync(0xffffffffu, s0, 1);
            s0 += __shfl_xor_sync(0xffffffffu, s0, 2);
            s1 += __shfl_xor_sync(0xffffffffu, s1, 1);
            s1 += __shfl_xor_sync(0xffffffffu, s1, 2);
            if ((lid & 3) == 0) {
                rsP[r0 * 2 + wn] = s0;
                rsP[r1 * 2 + wn] = s1;
            }
        }
    }
    __syncthreads();

    // ---- P2: den (warps 0-3) ----
    if (tid < CHK) {
        float rs = rsP[tid * 2 + 0] + rsP[tid * 2 + 1];
        float qz = 0.f;
#pragma unroll
        for (int d = 0; d < HD; d++) {
            float qv = __half2float(*(const __half*)(smem + OFF_QH + tid * QROWB + d * 2))
                     + __half2float(*(const __half*)(smem + OFF_QL + tid * QROWB + d * 2));
            qz += qv * zcs[d];
        }
        den[tid] = rs + qz + EPS_F;
    }

    // ---- P3: num = A@v + q@Sp, 3-pass each, warp tile 32x32 (4m x 2n) ----
    const int m_off3 = (wid & 3) * 32;
    const int n_off3 = (wid >> 2) * 32;
    float o[2][4][4];
#pragma unroll
    for (int mt = 0; mt < 2; mt++)
#pragma unroll
        for (int nt = 0; nt < 4; nt++)
#pragma unroll
            for (int e = 0; e < 4; e++) o[mt][nt][e] = 0.f;

    // (a) A @ v : K-dim = 128
#pragma unroll
    for (int ks = 0; ks < 8; ks++) {
        const int kcol = ks * 32;
        uint32_t bfh[2][4];
#pragma unroll
        for (int p = 0; p < 2; p++)
            ldmx4(bfh[p], sb + OFF_VTH + (n_off3 + p * 16 + b_r) * AROWB + kcol + b_c * 2);
        uint32_t af[2][4];
#pragma unroll
        for (int mt = 0; mt < 2; mt++)
            ldmx4(af[mt], sb + OFF_AH + (m_off3 + mt * 16 + a_r) * AROWB + kcol + a_c * 2);
#pragma unroll
        for (int mt = 0; mt < 2; mt++)
#pragma unroll
            for (int nt = 0; nt < 4; nt++)
                mma_f16(o[mt][nt], af[mt], &bfh[nt >> 1][(nt & 1) * 2]);
        uint32_t bfl[2][4];
#pragma unroll
        for (int p = 0; p < 2; p++)
            ldmx4(bfl[p], sb + OFF_VTL + (n_off3 + p * 16 + b_r) * AROWB + kcol + b_c * 2);
#pragma unroll
        for (int mt = 0; mt < 2; mt++)
#pragma unroll
            for (int nt = 0; nt < 4; nt++)
                mma_f16(o[mt][nt], af[mt], &bfl[nt >> 1][(nt & 1) * 2]);
#pragma unroll
        for (int mt = 0; mt < 2; mt++)
            ldmx4(af[mt], sb + OFF_AL + (m_off3 + mt * 16 + a_r) * AROWB + kcol + a_c * 2);
#pragma unroll
        for (int mt = 0; mt < 2; mt++)
#pragma unroll
            for (int nt = 0; nt < 4; nt++)
                mma_f16(o[mt][nt], af[mt], &bfh[nt >> 1][(nt & 1) * 2]);
    }

    // (b) q @ Sp : K-dim = 64
#pragma unroll
    for (int ks = 0; ks < 4; ks++) {
        const int kcol = ks * 32;
        uint32_t bfh[2][4];
#pragma unroll
        for (int p = 0; p < 2; p++)
            ldmx4(bfh[p], sb + OFF_SPTH + (n_off3 + p * 16 + b_r) * QROWB + kcol + b_c * 2);
        uint32_t af[2][4];
#pragma unroll
        for (int mt = 0; mt < 2; mt++)
            ldmx4(af[mt], sb + OFF_QH + (m_off3 + mt * 16 + a_r) * QROWB + kcol + a_c * 2);
#pragma unroll
        for (int mt = 0; mt < 2; mt++)
#pragma unroll
            for (int nt = 0; nt < 4; nt++)
                mma_f16(o[mt][nt], af[mt], &bfh[nt >> 1][(nt & 1) * 2]);
        uint32_t bfl[2][4];
#pragma unroll
        for (int p = 0; p < 2; p++)
            ldmx4(bfl[p], sb + OFF_SPTL + (n_off3 + p * 16 + b_r) * QROWB + kcol + b_c * 2);
#pragma unroll
        for (int mt = 0; mt < 2; mt++)
#pragma unroll
            for (int nt = 0; nt < 4; nt++)
                mma_f16(o[mt][nt], af[mt], &bfl[nt >> 1][(nt & 1) * 2]);
#pragma unroll
        for (int mt = 0; mt < 2; mt++)
            ldmx4(af[mt], sb + OFF_QL + (m_off3 + mt * 16 + a_r) * QROWB + kcol + a_c * 2);
#pragma unroll
        for (int mt = 0; mt < 2; mt++)
#pragma unroll
            for (int nt = 0; nt < 4; nt++)
                mma_f16(o[mt][nt], af[mt], &bfh[nt >> 1][(nt & 1) * 2]);
    }
    __syncthreads();   // den ready; qh/ql reads done (about to be overwritten)

    // ---- P4: divide by den, stage hi/lo into (reused) qh/ql regions ----
#pragma unroll
    for (int mt = 0; mt < 2; mt++) {
        const int r0 = m_off3 + mt * 16 + gr;
        const int r1 = r0 + 8;
        const float i0 = 1.f / den[r0];
        const float i1 = 1.f / den[r1];
#pragma unroll
        for (int nt = 0; nt < 4; nt++) {
            const int col = n_off3 + nt * 8 + gc2;
            float y0 = o[mt][nt][0] * i0;
            float y1 = o[mt][nt][1] * i0;
            float y2 = o[mt][nt][2] * i1;
            float y3 = o[mt][nt][3] * i1;
            __half h0 = __float2half(y0), h1 = __float2half(y1);
            __half h2 = __float2half(y2), h3 = __float2half(y3);
            *(__half2*)(smem + OFF_QH + r0 * QROWB + col * 2) = __halves2half2(h0, h1);
            *(__half2*)(smem + OFF_QH + r1 * QROWB + col * 2) = __halves2half2(h2, h3);
            *(__half2*)(smem + OFF_QL + r0 * QROWB + col * 2) =
                __halves2half2(__float2half(y0 - __half2float(h0)),
                               __float2half(y1 - __half2float(h1)));
            *(__half2*)(smem + OFF_QL + r1 * QROWB + col * 2) =
                __halves2half2(__float2half(y2 - __half2float(h2)),
                               __float2half(y3 - __half2float(h3)));
        }
    }
    __syncthreads();

    // ---- P5: coalesced global writes of hi/lo output ----
#pragma unroll
    for (int it = 0; it < 8; it++) {
        int idx = tid + it * 256;                 // 2048 half4 chunks
        int r = idx >> 4, c4 = (idx & 15) * 4;
        uint2 vh = *(const uint2*)(smem + OFF_QH + r * QROWB + c4 * 2);
        uint2 vl = *(const uint2*)(smem + OFF_QL + r * QROWB + c4 * 2);
        *reinterpret_cast<uint2*>(Oh + base + (size_t)r * EMB + c4) = vh;
        *reinterpret_cast<uint2*>(Ol + base + (size_t)r * EMB + c4) = vl;
    }
}

// ---------------- launch ----------------
extern "C" void kernel_launch(void* const* d_in, const int* in_sizes, int n_in,
                              void* d_out, int out_size)
{
    const float* x  = (const float*)d_in[0];
    const float* Wq = (const float*)d_in[1];
    const float* Wk = (const float*)d_in[2];
    const float* Wv = (const float*)d_in[3];
    const float* Wo = (const float*)d_in[4];
    const float* bo = (const float*)d_in[5];
    float* out = (float*)d_out;
    (void)in_sizes; (void)n_in; (void)out_size;

    float *pQ, *pK, *pV, *pS, *pSp, *pZ, *pZp;
    cudaGetSymbolAddress((void**)&pQ,  g_Q);
    cudaGetSymbolAddress((void**)&pK,  g_K);
    cudaGetSymbolAddress((void**)&pV,  g_V);
    cudaGetSymbolAddress((void**)&pS,  g_S);
    cudaGetSymbolAddress((void**)&pSp, g_Sp);
    cudaGetSymbolAddress((void**)&pZ,  g_z);
    cudaGetSymbolAddress((void**)&pZp, g_zp);

    __half *xh, *xl, *ah, *al, *wh;
    cudaGetSymbolAddress((void**)&xh, g_xh);
    cudaGetSymbolAddress((void**)&xl, g_xl);
    cudaGetSymbolAddress((void**)&ah, g_ah);
    cudaGetSymbolAddress((void**)&al, g_al);
    cudaGetSymbolAddress((void**)&wh, g_w);

    cudaFuncSetAttribute(mma_gemm_half<0>,
                         cudaFuncAttributeMaxDynamicSharedMemorySize, GEMM_SMEM);
    cudaFuncSetAttribute(mma_gemm_half<1>,
                         cudaFuncAttributeMaxDynamicSharedMemorySize, GEMM_SMEM);
    cudaFuncSetAttribute(attn_mma_kernel,
                         cudaFuncAttributeMaxDynamicSharedMemorySize, ATTN_SMEM);

    const int n4x = MROWS * EMB / 4;   // 1048576
    const int n4w = EMB * EMB / 4;     // 262144

    // operand conversion
    split_half_kernel<<<n4x / 256, 256>>>(x, xh, xl, n4x);
    conv_w_kernel<<<dim3(n4w / 256, 4), 256>>>(Wq, Wk, Wv, Wo, wh);

    // Fused Q/K/V projections (z selects weight; phi fused for z<2)
    dim3 qkv_grid(EMB / 128, MROWS / 128, 3);     // (8, 32, 3)
    mma_gemm_half<0><<<qkv_grid, 256, GEMM_SMEM>>>(xh, xl, wh, nullptr, pQ, pK, pV);

    // Chunked recurrent state: stats -> prefix -> tensor-core output (emits fp16 hi/lo)
    chunk_stats_kernel<<<BATCH * NH * NC, 256>>>(pK, pV, pS, pZ);
    prefix_kernel<<<BATCH * NH, 256>>>(pS, pZ, pSp, pZp);
    attn_mma_kernel<<<BATCH * NH * NC, 256, ATTN_SMEM>>>(pQ, pK, pV, pSp, pZp, ah, al);

    // Output projection + bias (reads attn hi/lo directly)
    dim3 o_grid(EMB / 128, MROWS / 128, 1);
    mma_gemm_half<1><<<o_grid, 256, GEMM_SMEM>>>(ah, al, wh + (size_t)3 * EMB * EMB, bo,
                                                 out, nullptr, nullptr);
}

// round 13
// speedup vs baseline: 3.5100x; 1.0118x over previous
#include <cuda_runtime.h>
#include <cuda_fp16.h>
#include <cstdint>
#include <cstddef>

// Problem constants (fixed by setup_inputs)
#define BATCH 2
#define TSEQ  2048
#define EMB   1024
#define NH    16
#define HD    64
#define CHK   128
#define NC    (TSEQ / CHK)          // 16
#define MROWS (BATCH * TSEQ)        // 4096
#define EPS_F 1e-5f

// ---------------- scratch (static device allocations) ----------------
__device__ float g_S [(size_t)BATCH * NH * NC * HD * HD];   // per-chunk  k^T v
__device__ float g_Sp[(size_t)BATCH * NH * NC * HD * HD];   // exclusive prefix
__device__ float g_z [(size_t)BATCH * NH * NC * HD];
__device__ float g_zp[(size_t)BATCH * NH * NC * HD];

// fp16 hi/lo operands
__device__ __half g_xh[(size_t)MROWS * EMB];
__device__ __half g_xl[(size_t)MROWS * EMB];
__device__ __half g_qh[(size_t)MROWS * EMB];
__device__ __half g_ql[(size_t)MROWS * EMB];
__device__ __half g_kh[(size_t)MROWS * EMB];
__device__ __half g_kl[(size_t)MROWS * EMB];
__device__ __half g_vh[(size_t)MROWS * EMB];
__device__ __half g_vl[(size_t)MROWS * EMB];
__device__ __half g_ah[(size_t)MROWS * EMB];   // attn output hi
__device__ __half g_al[(size_t)MROWS * EMB];   // attn output lo
__device__ __half g_w [(size_t)4 * EMB * EMB]; // Wq, Wk, Wv, Wo (fp16)

// ---------------- PTX helpers (arch-agnostic: valid on target sm_103) ----------------
__device__ __forceinline__ uint32_t smem_u32(const void* p) {
    uint32_t a;
    asm("{ .reg .u64 t; cvta.to.shared.u64 t, %1; cvt.u32.u64 %0, t; }"
        : "=r"(a) : "l"(p));
    return a;
}
__device__ __forceinline__ void cp16(uint32_t s, const void* g) {
    asm volatile("cp.async.cg.shared.global [%0], [%1], 16;" :: "r"(s), "l"(g) : "memory");
}
__device__ __forceinline__ void cp_commit() {
    asm volatile("cp.async.commit_group;" ::: "memory");
}
__device__ __forceinline__ void cp_wait0() {
    asm volatile("cp.async.wait_group 0;" ::: "memory");
}
__device__ __forceinline__ void cp_wait1() {
    asm volatile("cp.async.wait_group 1;" ::: "memory");
}
__device__ __forceinline__ void ldmx4(uint32_t* r, uint32_t addr) {
    asm volatile("ldmatrix.sync.aligned.m8n8.x4.shared.b16 {%0,%1,%2,%3}, [%4];"
                 : "=r"(r[0]), "=r"(r[1]), "=r"(r[2]), "=r"(r[3]) : "r"(addr));
}
__device__ __forceinline__ void ldmx4t(uint32_t* r, uint32_t addr) {
    asm volatile("ldmatrix.sync.aligned.m8n8.x4.trans.shared.b16 {%0,%1,%2,%3}, [%4];"
                 : "=r"(r[0]), "=r"(r[1]), "=r"(r[2]), "=r"(r[3]) : "r"(addr));
}
__device__ __forceinline__ void mma_f16(float* c, const uint32_t* a, const uint32_t* b) {
    asm volatile("mma.sync.aligned.m16n8k16.row.col.f32.f16.f16.f32 "
                 "{%0,%1,%2,%3},{%4,%5,%6,%7},{%8,%9},{%0,%1,%2,%3};"
                 : "+f"(c[0]), "+f"(c[1]), "+f"(c[2]), "+f"(c[3])
                 : "r"(a[0]), "r"(a[1]), "r"(a[2]), "r"(a[3]), "r"(b[0]), "r"(b[1]));
}

// ---------------- hi/lo fp16 split (x only) ----------------
__global__ __launch_bounds__(256)
void split_half_kernel(const float* __restrict__ in,
                       __half* __restrict__ hi, __half* __restrict__ lo, int n4)
{
    int i = blockIdx.x * 256 + threadIdx.x;
    if (i >= n4) return;
    float4 v = reinterpret_cast<const float4*>(in)[i];
    __half2 h01 = __floats2half2_rn(v.x, v.y);
    __half2 h23 = __floats2half2_rn(v.z, v.w);
    float2 f01 = __half22float2(h01);
    float2 f23 = __half22float2(h23);
    reinterpret_cast<__half2*>(hi)[2 * i + 0] = h01;
    reinterpret_cast<__half2*>(hi)[2 * i + 1] = h23;
    reinterpret_cast<__half2*>(lo)[2 * i + 0] = __floats2half2_rn(v.x - f01.x, v.y - f01.y);
    reinterpret_cast<__half2*>(lo)[2 * i + 1] = __floats2half2_rn(v.z - f23.x, v.w - f23.y);
}

// ---------------- fp16 convert for all 4 weights (one launch) ----------------
__global__ __launch_bounds__(256)
void conv_w_kernel(const float* __restrict__ Wq, const float* __restrict__ Wk,
                   const float* __restrict__ Wv, const float* __restrict__ Wo,
                   __half* __restrict__ dst)
{
    const int wsel = blockIdx.y;
    const float* src = (wsel == 0) ? Wq : (wsel == 1) ? Wk : (wsel == 2) ? Wv : Wo;
    int i = blockIdx.x * 256 + threadIdx.x;
    float4 v = reinterpret_cast<const float4*>(src)[i];
    __half2* o = reinterpret_cast<__half2*>(dst + (size_t)wsel * EMB * EMB);
    o[2 * i + 0] = __floats2half2_rn(v.x, v.y);
    o[2 * i + 1] = __floats2half2_rn(v.z, v.w);
}

// ---------------- mma.sync fp16 2-pass GEMM: C = act( A @ W^T ) ----------------
// MODE 0: fused QKV, emits fp16 hi/lo outputs (phi for z<2)
// MODE 1: output projection (+bias), emits fp32
#define KC        64
#define NKC       (EMB / KC)            // 16
#define ROW_HALF  72
#define ROW_B     (ROW_HALF * 2)        // 144
#define TILE_BY   (128 * ROW_B)         // 18432
#define STAGE_BY  (3 * TILE_BY)         // 55296
#define GEMM_SMEM (2 * STAGE_BY)        // 110592

template <int MODE>
__global__ __launch_bounds__(256, 2)
void mma_gemm_half(const __half* __restrict__ Ah, const __half* __restrict__ Al,
                   const __half* __restrict__ Wall, const float* __restrict__ bias,
                   float* __restrict__ Cf,
                   __half* __restrict__ OhQ, __half* __restrict__ OlQ,
                   __half* __restrict__ OhK, __half* __restrict__ OlK,
                   __half* __restrict__ OhV, __half* __restrict__ OlV)
{
    extern __shared__ char smem[];
    const uint32_t sb = smem_u32(smem);

    const int z = (MODE == 0) ? blockIdx.z : 0;
    const __half* B = Wall + (size_t)z * EMB * EMB;
    __half* oh = (z == 0) ? OhQ : (z == 1) ? OhK : OhV;
    __half* ol = (z == 0) ? OlQ : (z == 1) ? OlK : OlV;
    const int do_phi = (MODE == 0) && (z < 2);

    const int tid = threadIdx.x;
    const int wid = tid >> 5;
    const int lid = tid & 31;
    const int bm  = blockIdx.y * 128;
    const int bn  = blockIdx.x * 128;

    const int m_off = (wid & 3) * 32;
    const int n_off = (wid >> 2) * 64;

    const int q   = lid >> 3;
    const int a_r = ((q & 1) << 3) + (lid & 7);
    const int a_c = (q >> 1) << 3;
    const int b_r = ((q >> 1) << 3) + (lid & 7);
    const int b_c = (q & 1) << 3;

    auto load_chunk = [&](int kc, int stg) {
#pragma unroll
        for (int it = 0; it < 12; it++) {
            int idx = tid + it * 256;
            int t = idx >> 10;
            int r = (idx >> 3) & 127;
            int c = idx & 7;
            uint32_t saddr = sb + stg * STAGE_BY + t * TILE_BY + r * ROW_B + c * 16;
            const __half* src = (t == 0) ? Ah : (t == 1) ? Al : B;
            int grow = (t < 2) ? (bm + r) : (bn + r);
            cp16(saddr, src + (size_t)grow * EMB + kc * KC + c * 8);
        }
        cp_commit();
    };

    float acc[2][8][4];
#pragma unroll
    for (int mt = 0; mt < 2; mt++)
#pragma unroll
        for (int nt = 0; nt < 8; nt++)
#pragma unroll
            for (int e = 0; e < 4; e++) acc[mt][nt][e] = 0.f;

    load_chunk(0, 0);

    for (int kc = 0; kc < NKC; kc++) {
        if (kc + 1 < NKC) { load_chunk(kc + 1, (kc + 1) & 1); cp_wait1(); }
        else              { cp_wait0(); }
        __syncthreads();

        const uint32_t uAh = sb + (kc & 1) * STAGE_BY;
        const uint32_t uAl = uAh + TILE_BY;
        const uint32_t uB  = uAl + TILE_BY;

#pragma unroll
        for (int ks = 0; ks < 4; ks++) {
            const int kcol2 = ks * 32;

            uint32_t bf[4][4];
#pragma unroll
            for (int p = 0; p < 4; p++)
                ldmx4(bf[p], uB + (n_off + p * 16 + b_r) * ROW_B + kcol2 + b_c * 2);

            uint32_t af[2][4];
#pragma unroll
            for (int mt = 0; mt < 2; mt++)
                ldmx4(af[mt], uAh + (m_off + mt * 16 + a_r) * ROW_B + kcol2 + a_c * 2);
#pragma unroll
            for (int mt = 0; mt < 2; mt++)
#pragma unroll
                for (int nt = 0; nt < 8; nt++)
                    mma_f16(acc[mt][nt], af[mt], &bf[nt >> 1][(nt & 1) * 2]);

#pragma unroll
            for (int mt = 0; mt < 2; mt++)
                ldmx4(af[mt], uAl + (m_off + mt * 16 + a_r) * ROW_B + kcol2 + a_c * 2);
#pragma unroll
            for (int mt = 0; mt < 2; mt++)
#pragma unroll
                for (int nt = 0; nt < 8; nt++)
                    mma_f16(acc[mt][nt], af[mt], &bf[nt >> 1][(nt & 1) * 2]);
        }
        __syncthreads();
    }

    const int gr  = lid >> 2;
    const int gc2 = (lid & 3) * 2;
#pragma unroll
    for (int mt = 0; mt < 2; mt++) {
#pragma unroll
        for (int nt = 0; nt < 8; nt++) {
            int row0 = bm + m_off + mt * 16 + gr;
            int col  = bn + n_off + nt * 8 + gc2;
            float v0 = acc[mt][nt][0], v1 = acc[mt][nt][1];
            float v2 = acc[mt][nt][2], v3 = acc[mt][nt][3];
            if (MODE == 0) {
                if (do_phi) {
                    v0 = (v0 > 0.f) ? (v0 + 1.f) : expf(v0);
                    v1 = (v1 > 0.f) ? (v1 + 1.f) : expf(v1);
                    v2 = (v2 > 0.f) ? (v2 + 1.f) : expf(v2);
                    v3 = (v3 > 0.f) ? (v3 + 1.f) : expf(v3);
                }
                __half h0 = __float2half(v0), h1 = __float2half(v1);
                __half h2 = __float2half(v2), h3 = __float2half(v3);
                *(__half2*)(oh + (size_t)row0 * EMB + col)       = __halves2half2(h0, h1);
                *(__half2*)(oh + (size_t)(row0 + 8) * EMB + col) = __halves2half2(h2, h3);
                *(__half2*)(ol + (size_t)row0 * EMB + col) =
                    __halves2half2(__float2half(v0 - __half2float(h0)),
                                   __float2half(v1 - __half2float(h1)));
                *(__half2*)(ol + (size_t)(row0 + 8) * EMB + col) =
                    __halves2half2(__float2half(v2 - __half2float(h2)),
                                   __float2half(v3 - __half2float(h3)));
            } else {
                float2 bv = *reinterpret_cast<const float2*>(bias + col);
                *reinterpret_cast<float2*>(Cf + (size_t)row0 * EMB + col) =
                    make_float2(v0 + bv.x, v1 + bv.y);
                *reinterpret_cast<float2*>(Cf + (size_t)(row0 + 8) * EMB + col) =
                    make_float2(v2 + bv.x, v3 + bv.y);
            }
        }
    }
}

// ---------------- Phase A (tensor-core): S_c = k^T v,  z_c = sum_j k ----------------
// K,V tiles fp16 hi/lo, row-major [j=128][d=64], rows padded to 72 halves.
// k^T v via ldmatrix.trans (A uses (b_r,b_c) addrs, B uses (a_r,a_c)), 3-pass hi/lo.
#define CS_KH 0
#define CS_KL 18432
#define CS_VH 36864
#define CS_VL 55296
#define CS_SMEM 73728

__global__ __launch_bounds__(256)
void chunk_stats_tc(const __half* __restrict__ Kh, const __half* __restrict__ Kl,
                    const __half* __restrict__ Vh, const __half* __restrict__ Vl,
                    float* __restrict__ gS, float* __restrict__ gZ)
{
    extern __shared__ char smem[];
    const uint32_t sb = smem_u32(smem);

    const int blk = blockIdx.x;
    const int c   = blk % NC;
    const int bh  = blk / NC;
    const int b   = bh / NH;
    const int h   = bh % NH;
    const int tid = threadIdx.x;
    const int wid = tid >> 5;
    const int lid = tid & 31;

    const size_t base = ((size_t)(b * TSEQ) + (size_t)c * CHK) * EMB + (size_t)h * HD;

    const __half* srcs[4] = {Kh + base, Kl + base, Vh + base, Vl + base};
    const uint32_t dofs[4] = {CS_KH, CS_KL, CS_VH, CS_VL};
#pragma unroll
    for (int it = 0; it < 16; it++) {
        int idx = tid + it * 256;
        int t = idx >> 10, r = (idx >> 3) & 127, c8 = (idx & 7) * 8;
        uint4 v = *reinterpret_cast<const uint4*>(srcs[t] + (size_t)r * EMB + c8);
        *reinterpret_cast<uint4*>(smem + dofs[t] + r * ROW_B + c8 * 2) = v;
    }
    __syncthreads();

    const int q   = lid >> 3;
    const int a_r = ((q & 1) << 3) + (lid & 7);
    const int a_c = (q >> 1) << 3;
    const int b_r = ((q >> 1) << 3) + (lid & 7);
    const int b_c = (q & 1) << 3;

    const int m_off = (wid & 3) * 16;      // d rows of S
    const int n_off = (wid >> 2) * 32;     // e cols of S

    float acc[4][4];
#pragma unroll
    for (int nt = 0; nt < 4; nt++)
#pragma unroll
        for (int e = 0; e < 4; e++) acc[nt][e] = 0.f;

#pragma unroll
    for (int ks = 0; ks < 8; ks++) {
        const int jb = ks * 16;
        // A = K^T (trans load): stored row = j (k-dim), col = d (m-dim)
        uint32_t afh[4], afl[4];
        ldmx4t(afh, sb + CS_KH + (jb + b_r) * ROW_B + (m_off + b_c) * 2);
        // B = V^T (trans load): stored row = j (k-dim), col = e (n-dim)
        uint32_t bfh[2][4];
#pragma unroll
        for (int p = 0; p < 2; p++)
            ldmx4t(bfh[p], sb + CS_VH + (jb + a_r) * ROW_B + (n_off + p * 16 + a_c) * 2);
#pragma unroll
        for (int nt = 0; nt < 4; nt++)
            mma_f16(acc[nt], afh, &bfh[nt >> 1][(nt & 1) * 2]);

        uint32_t bfl[2][4];
#pragma unroll
        for (int p = 0; p < 2; p++)
            ldmx4t(bfl[p], sb + CS_VL + (jb + a_r) * ROW_B + (n_off + p * 16 + a_c) * 2);
#pragma unroll
        for (int nt = 0; nt < 4; nt++)
            mma_f16(acc[nt], afh, &bfl[nt >> 1][(nt & 1) * 2]);

        ldmx4t(afl, sb + CS_KL + (jb + b_r) * ROW_B + (m_off + b_c) * 2);
#pragma unroll
        for (int nt = 0; nt < 4; nt++)
            mma_f16(acc[nt], afl, &bfh[nt >> 1][(nt & 1) * 2]);
    }

    const int gr  = lid >> 2;
    const int gc2 = (lid & 3) * 2;
    float* Sout = gS + (size_t)blk * (HD * HD);
#pragma unroll
    for (int nt = 0; nt < 4; nt++) {
        int row0 = m_off + gr;
        int col  = n_off + nt * 8 + gc2;
        *reinterpret_cast<float2*>(Sout + (size_t)row0 * HD + col) =
            make_float2(acc[nt][0], acc[nt][1]);
        *reinterpret_cast<float2*>(Sout + (size_t)(row0 + 8) * HD + col) =
            make_float2(acc[nt][2], acc[nt][3]);
    }

    if (tid < HD) {
        const __half* kh = reinterpret_cast<const __half*>(smem + CS_KH);
        const __half* kl = reinterpret_cast<const __half*>(smem + CS_KL);
        float zsum = 0.f;
        for (int j = 0; j < CHK; j++)
            zsum += __half2float(kh[j * ROW_HALF + tid]) + __half2float(kl[j * ROW_HALF + tid]);
        gZ[(size_t)blk * HD + tid] = zsum;
    }
}

// ---------------- Phase B: exclusive prefix over chunks ----------------
__global__ __launch_bounds__(256)
void prefix_kernel(const float* __restrict__ gS, const float* __restrict__ gZ,
                   float* __restrict__ gSp, float* __restrict__ gZp)
{
    const int bh  = blockIdx.x;
    const int tid = threadIdx.x;

    float acc[16];
#pragma unroll
    for (int i = 0; i < 16; i++) acc[i] = 0.f;

    for (int c = 0; c < NC; c++) {
        size_t off = ((size_t)bh * NC + c) * (HD * HD);
#pragma unroll
        for (int i = 0; i < 16; i++) {
            gSp[off + tid * 16 + i] = acc[i];
            acc[i] += gS[off + tid * 16 + i];
        }
    }
    if (tid < HD) {
        float z = 0.f;
        for (int c = 0; c < NC; c++) {
            size_t off = ((size_t)bh * NC + c) * HD;
            gZp[off + tid] = z;
            z += gZ[off + tid];
        }
    }
}

// ---------------- Phase C: tensor-core per-chunk output ----------------
// out = ( A@v + q@Sp ) / ( rowsum(A) + q.zp + eps ),  A = (q k^T) masked
// Q,K,V arrive as fp16 hi/lo; V and Sp consumed row-major via ldmatrix.trans.
#define QROWB  144
#define AROWB  272
#define OFF_QH   0
#define OFF_QL   18432
#define OFF_KH   36864
#define OFF_KL   55296
#define OFF_AH   73728
#define OFF_AL   108544
#define OFF_VH   143360
#define OFF_VL   161792
#define OFF_SPH  180224
#define OFF_SPL  189440
#define OFF_ZC   198656
#define OFF_DEN  198912
#define OFF_RSP  199424
#define ATTN_SMEM 200448

__global__ __launch_bounds__(256, 1)
void attn_mma_kernel(const __half* __restrict__ Qh_g, const __half* __restrict__ Ql_g,
                     const __half* __restrict__ Kh_g, const __half* __restrict__ Kl_g,
                     const __half* __restrict__ Vh_g, const __half* __restrict__ Vl_g,
                     const float* __restrict__ gSp, const float* __restrict__ gZp,
                     __half* __restrict__ Oh, __half* __restrict__ Ol)
{
    extern __shared__ char smem[];
    const uint32_t sb = smem_u32(smem);

    const int blk = blockIdx.x;
    const int c   = blk % NC;
    const int bh  = blk / NC;
    const int b   = bh / NH;
    const int h   = bh % NH;
    const int tid = threadIdx.x;
    const int wid = tid >> 5;
    const int lid = tid & 31;

    const size_t base = ((size_t)(b * TSEQ) + (size_t)c * CHK) * EMB + (size_t)h * HD;

    float* zcs  = reinterpret_cast<float*>(smem + OFF_ZC);
    float* den  = reinterpret_cast<float*>(smem + OFF_DEN);
    float* rsP  = reinterpret_cast<float*>(smem + OFF_RSP);   // [128][2]

    // ---- P0: coalesced fp16 copies (Q,K,V) + Sp fp32->hi/lo split ----
    {
        const __half* srcs[6] = {Qh_g + base, Ql_g + base, Kh_g + base,
                                 Kl_g + base, Vh_g + base, Vl_g + base};
        const uint32_t dofs[6] = {OFF_QH, OFF_QL, OFF_KH, OFF_KL, OFF_VH, OFF_VL};
#pragma unroll
        for (int it = 0; it < 24; it++) {
            int idx = tid + it * 256;
            int t = idx >> 10, r = (idx >> 3) & 127, c8 = (idx & 7) * 8;
            uint4 v = *reinterpret_cast<const uint4*>(srcs[t] + (size_t)r * EMB + c8);
            *reinterpret_cast<uint4*>(smem + dofs[t] + r * QROWB + c8 * 2) = v;
        }
    }
#pragma unroll
    for (int it = 0; it < 4; it++) {
        int idx = tid + it * 256;                 // 1024 float4 slots
        int d = idx >> 4, e4 = (idx & 15) * 4;
        float4 v = *(const float4*)(gSp + (size_t)blk * (HD * HD) + (size_t)d * HD + e4);
        __half h0 = __float2half(v.x), h1 = __float2half(v.y);
        __half h2 = __float2half(v.z), h3 = __float2half(v.w);
        char* ph = smem + OFF_SPH + d * QROWB + e4 * 2;
        char* pl = smem + OFF_SPL + d * QROWB + e4 * 2;
        *(__half2*)(ph)     = __halves2half2(h0, h1);
        *(__half2*)(ph + 4) = __halves2half2(h2, h3);
        *(__half2*)(pl)     = __halves2half2(__float2half(v.x - __half2float(h0)),
                                             __float2half(v.y - __half2float(h1)));
        *(__half2*)(pl + 4) = __halves2half2(__float2half(v.z - __half2float(h2)),
                                             __float2half(v.w - __half2float(h3)));
    }
    if (tid < HD) zcs[tid] = gZp[(size_t)blk * HD + tid];
    __syncthreads();

    const int q   = lid >> 3;
    const int a_r = ((q & 1) << 3) + (lid & 7);
    const int a_c = (q >> 1) << 3;
    const int b_r = ((q >> 1) << 3) + (lid & 7);
    const int b_c = (q & 1) << 3;
    const int gr  = lid >> 2;
    const int gc2 = (lid & 3) * 2;

    // ---- P1: A = q k^T, 3-pass, warp tile 32x64 (4m x 2n warps) ----
    {
        const int m_off = (wid & 3) * 32;
        const int n_off = (wid >> 2) * 64;
        const int wn    = wid >> 2;

        float acc[2][8][4];
#pragma unroll
        for (int mt = 0; mt < 2; mt++)
#pragma unroll
            for (int nt = 0; nt < 8; nt++)
#pragma unroll
                for (int e = 0; e < 4; e++) acc[mt][nt][e] = 0.f;

#pragma unroll
        for (int ks = 0; ks < 4; ks++) {
            const int kcol = ks * 32;
            uint32_t bfh[4][4];
#pragma unroll
            for (int p = 0; p < 4; p++)
                ldmx4(bfh[p], sb + OFF_KH + (n_off + p * 16 + b_r) * QROWB + kcol + b_c * 2);
            uint32_t af[2][4];
#pragma unroll
            for (int mt = 0; mt < 2; mt++)
                ldmx4(af[mt], sb + OFF_QH + (m_off + mt * 16 + a_r) * QROWB + kcol + a_c * 2);
#pragma unroll
            for (int mt = 0; mt < 2; mt++)
#pragma unroll
                for (int nt = 0; nt < 8; nt++)
                    mma_f16(acc[mt][nt], af[mt], &bfh[nt >> 1][(nt & 1) * 2]);
            uint32_t bfl[4][4];
#pragma unroll
            for (int p = 0; p < 4; p++)
                ldmx4(bfl[p], sb + OFF_KL + (n_off + p * 16 + b_r) * QROWB + kcol + b_c * 2);
#pragma unroll
            for (int mt = 0; mt < 2; mt++)
#pragma unroll
                for (int nt = 0; nt < 8; nt++)
                    mma_f16(acc[mt][nt], af[mt], &bfl[nt >> 1][(nt & 1) * 2]);
#pragma unroll
            for (int mt = 0; mt < 2; mt++)
                ldmx4(af[mt], sb + OFF_QL + (m_off + mt * 16 + a_r) * QROWB + kcol + a_c * 2);
#pragma unroll
            for (int mt = 0; mt < 2; mt++)
#pragma unroll
                for (int nt = 0; nt < 8; nt++)
                    mma_f16(acc[mt][nt], af[mt], &bfh[nt >> 1][(nt & 1) * 2]);
        }

        // mask + rowsum + hi/lo store of A
#pragma unroll
        for (int mt = 0; mt < 2; mt++) {
            const int r0 = m_off + mt * 16 + gr;
            const int r1 = r0 + 8;
            float s0 = 0.f, s1 = 0.f;
#pragma unroll
            for (int nt = 0; nt < 8; nt++) {
                const int col = n_off + nt * 8 + gc2;
                float c0 = (col     <= r0) ? acc[mt][nt][0] : 0.f;
                float c1 = (col + 1 <= r0) ? acc[mt][nt][1] : 0.f;
                float c2 = (col     <= r1) ? acc[mt][nt][2] : 0.f;
                float c3 = (col + 1 <= r1) ? acc[mt][nt][3] : 0.f;
                s0 += c0 + c1;
                s1 += c2 + c3;
                __half h0 = __float2half(c0), h1 = __float2half(c1);
                __half h2 = __float2half(c2), h3 = __float2half(c3);
                *(__half2*)(smem + OFF_AH + r0 * AROWB + col * 2) = __halves2half2(h0, h1);
                *(__half2*)(smem + OFF_AH + r1 * AROWB + col * 2) = __halves2half2(h2, h3);
                *(__half2*)(smem + OFF_AL + r0 * AROWB + col * 2) =
                    __halves2half2(__float2half(c0 - __half2float(h0)),
                                   __float2half(c1 - __half2float(h1)));
                *(__half2*)(smem + OFF_AL + r1 * AROWB + col * 2) =
                    __halves2half2(__float2half(c2 - __half2float(h2)),
                                   __float2half(c3 - __half2float(h3)));
            }
            s0 += __shfl_xor_sync(0xffffffffu, s0, 1);
            s0 += __shfl_xor_sync(0xffffffffu, s0, 2);
            s1 += __shfl_xor_sync(0xffffffffu, s1, 1);
            s1 += __shfl_xor_sync(0xffffffffu, s1, 2);
            if ((lid & 3) == 0) {
                rsP[r0 * 2 + wn] = s0;
                rsP[r1 * 2 + wn] = s1;
            }
        }
    }
    __syncthreads();

    // ---- P2: den ----
    if (tid < CHK) {
        float rs = rsP[tid * 2 + 0] + rsP[tid * 2 + 1];
        float qz = 0.f;
#pragma unroll
        for (int d = 0; d < HD; d++) {
            float qv = __half2float(*(const __half*)(smem + OFF_QH + tid * QROWB + d * 2))
                     + __half2float(*(const __half*)(smem + OFF_QL + tid * QROWB + d * 2));
            qz += qv * zcs[d];
        }
        den[tid] = rs + qz + EPS_F;
    }

    // ---- P3: num = A@v + q@Sp (B operands row-major via ldmatrix.trans) ----
    const int m_off3 = (wid & 3) * 32;
    const int n_off3 = (wid >> 2) * 32;
    float o[2][4][4];
#pragma unroll
    for (int mt = 0; mt < 2; mt++)
#pragma unroll
        for (int nt = 0; nt < 4; nt++)
#pragma unroll
            for (int e = 0; e < 4; e++) o[mt][nt][e] = 0.f;

    // (a) A @ v : K-dim = 128 (j), V stored [j][e] row-major -> trans B loads
#pragma unroll
    for (int ks = 0; ks < 8; ks++) {
        const int jb = ks * 16;
        const int kcol = ks * 32;
        uint32_t bfh[2][4];
#pragma unroll
        for (int p = 0; p < 2; p++)
            ldmx4t(bfh[p], sb + OFF_VH + (jb + a_r) * QROWB + (n_off3 + p * 16 + a_c) * 2);
        uint32_t af[2][4];
#pragma unroll
        for (int mt = 0; mt < 2; mt++)
            ldmx4(af[mt], sb + OFF_AH + (m_off3 + mt * 16 + a_r) * AROWB + kcol + a_c * 2);
#pragma unroll
        for (int mt = 0; mt < 2; mt++)
#pragma unroll
            for (int nt = 0; nt < 4; nt++)
                mma_f16(o[mt][nt], af[mt], &bfh[nt >> 1][(nt & 1) * 2]);
        uint32_t bfl[2][4];
#pragma unroll
        for (int p = 0; p < 2; p++)
            ldmx4t(bfl[p], sb + OFF_VL + (jb + a_r) * QROWB + (n_off3 + p * 16 + a_c) * 2);
#pragma unroll
        for (int mt = 0; mt < 2; mt++)
#pragma unroll
            for (int nt = 0; nt < 4; nt++)
                mma_f16(o[mt][nt], af[mt], &bfl[nt >> 1][(nt & 1) * 2]);
#pragma unroll
        for (int mt = 0; mt < 2; mt++)
            ldmx4(af[mt], sb + OFF_AL + (m_off3 + mt * 16 + a_r) * AROWB + kcol + a_c * 2);
#pragma unroll
        for (int mt = 0; mt < 2; mt++)
#pragma unroll
            for (int nt = 0; nt < 4; nt++)
                mma_f16(o[mt][nt], af[mt], &bfh[nt >> 1][(nt & 1) * 2]);
    }

    // (b) q @ Sp : K-dim = 64 (d), Sp stored [d][e] row-major -> trans B loads
#pragma unroll
    for (int ks = 0; ks < 4; ks++) {
        const int db = ks * 16;
        const int kcol = ks * 32;
        uint32_t bfh[2][4];
#pragma unroll
        for (int p = 0; p < 2; p++)
            ldmx4t(bfh[p], sb + OFF_SPH + (db + a_r) * QROWB + (n_off3 + p * 16 + a_c) * 2);
        uint32_t af[2][4];
#pragma unroll
        for (int mt = 0; mt < 2; mt++)
            ldmx4(af[mt], sb + OFF_QH + (m_off3 + mt * 16 + a_r) * QROWB + kcol + a_c * 2);
#pragma unroll
        for (int mt = 0; mt < 2; mt++)
#pragma unroll
            for (int nt = 0; nt < 4; nt++)
                mma_f16(o[mt][nt], af[mt], &bfh[nt >> 1][(nt & 1) * 2]);
        uint32_t bfl[2][4];
#pragma unroll
        for (int p = 0; p < 2; p++)
            ldmx4t(bfl[p], sb + OFF_SPL + (db + a_r) * QROWB + (n_off3 + p * 16 + a_c) * 2);
#pragma unroll
        for (int mt = 0; mt < 2; mt++)
#pragma unroll
            for (int nt = 0; nt < 4; nt++)
                mma_f16(o[mt][nt], af[mt], &bfl[nt >> 1][(nt & 1) * 2]);
#pragma unroll
        for (int mt = 0; mt < 2; mt++)
            ldmx4(af[mt], sb + OFF_QL + (m_off3 + mt * 16 + a_r) * QROWB + kcol + a_c * 2);
#pragma unroll
        for (int mt = 0; mt < 2; mt++)
#pragma unroll
            for (int nt = 0; nt < 4; nt++)
                mma_f16(o[mt][nt], af[mt], &bfh[nt >> 1][(nt & 1) * 2]);
    }
    __syncthreads();   // den ready; QH/QL reads done (about to be overwritten)

    // ---- P4: divide by den, stage hi/lo into (reused) QH/QL regions ----
#pragma unroll
    for (int mt = 0; mt < 2; mt++) {
        const int r0 = m_off3 + mt * 16 + gr;
        const int r1 = r0 + 8;
        const float i0 = 1.f / den[r0];
        const float i1 = 1.f / den[r1];
#pragma unroll
        for (int nt = 0; nt < 4; nt++) {
            const int col = n_off3 + nt * 8 + gc2;
            float y0 = o[mt][nt][0] * i0;
            float y1 = o[mt][nt][1] * i0;
            float y2 = o[mt][nt][2] * i1;
            float y3 = o[mt][nt][3] * i1;
            __half h0 = __float2half(y0), h1 = __float2half(y1);
            __half h2 = __float2half(y2), h3 = __float2half(y3);
            *(__half2*)(smem + OFF_QH + r0 * QROWB + col * 2) = __halves2half2(h0, h1);
            *(__half2*)(smem + OFF_QH + r1 * QROWB + col * 2) = __halves2half2(h2, h3);
            *(__half2*)(smem + OFF_QL + r0 * QROWB + col * 2) =
                __halves2half2(__float2half(y0 - __half2float(h0)),
                               __float2half(y1 - __half2float(h1)));
            *(__half2*)(smem + OFF_QL + r1 * QROWB + col * 2) =
                __halves2half2(__float2half(y2 - __half2float(h2)),
                               __float2half(y3 - __half2float(h3)));
        }
    }
    __syncthreads();

    // ---- P5: coalesced global writes of hi/lo output ----
#pragma unroll
    for (int it = 0; it < 8; it++) {
        int idx = tid + it * 256;                 // 2048 half4 chunks
        int r = idx >> 4, c4 = (idx & 15) * 4;
        uint2 vh = *(const uint2*)(smem + OFF_QH + r * QROWB + c4 * 2);
        uint2 vl = *(const uint2*)(smem + OFF_QL + r * QROWB + c4 * 2);
        *reinterpret_cast<uint2*>(Oh + base + (size_t)r * EMB + c4) = vh;
        *reinterpret_cast<uint2*>(Ol + base + (size_t)r * EMB + c4) = vl;
    }
}

// ---------------- launch ----------------
extern "C" void kernel_launch(void* const* d_in, const int* in_sizes, int n_in,
                              void* d_out, int out_size)
{
    const float* x  = (const float*)d_in[0];
    const float* Wq = (const float*)d_in[1];
    const float* Wk = (const float*)d_in[2];
    const float* Wv = (const float*)d_in[3];
    const float* Wo = (const float*)d_in[4];
    const float* bo = (const float*)d_in[5];
    float* out = (float*)d_out;
    (void)in_sizes; (void)n_in; (void)out_size;

    float *pS, *pSp, *pZ, *pZp;
    cudaGetSymbolAddress((void**)&pS,  g_S);
    cudaGetSymbolAddress((void**)&pSp, g_Sp);
    cudaGetSymbolAddress((void**)&pZ,  g_z);
    cudaGetSymbolAddress((void**)&pZp, g_zp);

    __half *xh, *xl, *qh_, *ql_, *kh_, *kl_, *vh_, *vl_, *ah, *al, *wh;
    cudaGetSymbolAddress((void**)&xh,  g_xh);
    cudaGetSymbolAddress((void**)&xl,  g_xl);
    cudaGetSymbolAddress((void**)&qh_, g_qh);
    cudaGetSymbolAddress((void**)&ql_, g_ql);
    cudaGetSymbolAddress((void**)&kh_, g_kh);
    cudaGetSymbolAddress((void**)&kl_, g_kl);
    cudaGetSymbolAddress((void**)&vh_, g_vh);
    cudaGetSymbolAddress((void**)&vl_, g_vl);
    cudaGetSymbolAddress((void**)&ah,  g_ah);
    cudaGetSymbolAddress((void**)&al,  g_al);
    cudaGetSymbolAddress((void**)&wh,  g_w);

    cudaFuncSetAttribute(mma_gemm_half<0>,
                         cudaFuncAttributeMaxDynamicSharedMemorySize, GEMM_SMEM);
    cudaFuncSetAttribute(mma_gemm_half<1>,
                         cudaFuncAttributeMaxDynamicSharedMemorySize, GEMM_SMEM);
    cudaFuncSetAttribute(chunk_stats_tc,
                         cudaFuncAttributeMaxDynamicSharedMemorySize, CS_SMEM);
    cudaFuncSetAttribute(attn_mma_kernel,
                         cudaFuncAttributeMaxDynamicSharedMemorySize, ATTN_SMEM);

    const int n4x = MROWS * EMB / 4;   // 1048576
    const int n4w = EMB * EMB / 4;     // 262144

    // operand conversion
    split_half_kernel<<<n4x / 256, 256>>>(x, xh, xl, n4x);
    conv_w_kernel<<<dim3(n4w / 256, 4), 256>>>(Wq, Wk, Wv, Wo, wh);

    // Fused Q/K/V projections -> fp16 hi/lo (phi fused for z<2)
    dim3 qkv_grid(EMB / 128, MROWS / 128, 3);     // (8, 32, 3)
    mma_gemm_half<0><<<qkv_grid, 256, GEMM_SMEM>>>(xh, xl, wh, nullptr, nullptr,
                                                   qh_, ql_, kh_, kl_, vh_, vl_);

    // Chunked recurrent state: tc stats -> prefix -> tc output (emits fp16 hi/lo)
    chunk_stats_tc<<<BATCH * NH * NC, 256, CS_SMEM>>>(kh_, kl_, vh_, vl_, pS, pZ);
    prefix_kernel<<<BATCH * NH, 256>>>(pS, pZ, pSp, pZp);
    attn_mma_kernel<<<BATCH * NH * NC, 256, ATTN_SMEM>>>(qh_, ql_, kh_, kl_, vh_, vl_,
                                                         pSp, pZp, ah, al);

    // Output projection + bias (fp32 out)
    dim3 o_grid(EMB / 128, MROWS / 128, 1);
    mma_gemm_half<1><<<o_grid, 256, GEMM_SMEM>>>(ah, al, wh + (size_t)3 * EMB * EMB, bo,
                                                 out, nullptr, nullptr, nullptr,
                                                 nullptr, nullptr, nullptr);
}